// round 3
// baseline (speedup 1.0000x reference)
#include <cuda_runtime.h>
#include <cuda_bf16.h>

#define N_NODES_MAX 50000
#define N_EDGES_MAX 800000
#define IN_CH 256
#define OUT_CH 64
#define NEG_BIG -9e15f

// ---------------- scratch (device globals: allocation-free) ----------------
__device__ float g_wh[(size_t)N_NODES_MAX * OUT_CH];   // 12.8 MB
__device__ float g_es[N_NODES_MAX];                    // e_src per node
__device__ float g_ed[N_NODES_MAX];                    // e_dst per node
__device__ float g_s[N_EDGES_MAX];                     // score, then exp(s-max)
__device__ int   g_src[N_EDGES_MAX];                   // decoded int32 src
__device__ int   g_dst[N_EDGES_MAX];                   // decoded int32 dst
__device__ float g_max;
__device__ float g_sum;
__device__ int   g_is64;

// ---------------- kernel A: detect edge-index dtype ----------------
// int64 indices < 2^31 have all-zero high words; int32 data has real random
// values at odd word positions. Check the first 256 words.
__global__ void detect_kernel(const unsigned int* __restrict__ ei_w) {
    if (threadIdx.x == 0) {
        unsigned int any = 0;
        for (int i = 1; i < 256; i += 2) any |= ei_w[i];
        g_is64 = (any == 0) ? 1 : 0;
    }
}

// ---------------- kernel 0: init output + softmax scalars ----------------
__global__ void init_kernel(float* __restrict__ out, int total) {
    int gtid = blockIdx.x * blockDim.x + threadIdx.x;
    if (gtid == 0) { g_max = NEG_BIG; g_sum = 0.0f; }
    for (int i = gtid; i < total; i += gridDim.x * blockDim.x) out[i] = 0.0f;
}

// ---------------- kernel 1: wh = x @ W, e_src = wh@a[:64], e_dst = wh@a[64:] ----
// 128 threads/block, each thread computes one full node row (64 outputs).
__global__ __launch_bounds__(128) void gemm_kernel(
    const float* __restrict__ x, const float* __restrict__ W,
    const float* __restrict__ a, int n)
{
    __shared__ float xs[128][33];     // padded: conflict-free xs[tid][k]
    __shared__ float ws[32][64];
    __shared__ float as[2 * OUT_CH];

    const int tid  = threadIdx.x;
    const int row0 = blockIdx.x * 128;
    const int row  = row0 + tid;

    as[tid] = a[tid];   // 128 threads, 128 values

    float acc[OUT_CH];
#pragma unroll
    for (int j = 0; j < OUT_CH; j++) acc[j] = 0.0f;

    for (int kc = 0; kc < IN_CH; kc += 32) {
        __syncthreads();
        // x tile: 128 rows x 32 cols, coalesced 32-float segments
#pragma unroll
        for (int i = 0; i < 32; i++) {
            int idx = i * 128 + tid;
            int r = idx >> 5, c = idx & 31;
            int gr = row0 + r;
            xs[r][c] = (gr < n) ? x[(size_t)gr * IN_CH + kc + c] : 0.0f;
        }
        // W tile: 32 x 64, coalesced
#pragma unroll
        for (int i = 0; i < 16; i++) {
            int idx = i * 128 + tid;
            int r = idx >> 6, c = idx & 63;
            ws[r][c] = W[(size_t)(kc + r) * OUT_CH + c];
        }
        __syncthreads();

#pragma unroll 8
        for (int k = 0; k < 32; k++) {
            float xv = xs[tid][k];
            const float4* wrow = reinterpret_cast<const float4*>(ws[k]);
#pragma unroll
            for (int j = 0; j < 16; j++) {
                float4 wv = wrow[j];          // warp-uniform -> smem broadcast
                acc[4 * j + 0] += xv * wv.x;
                acc[4 * j + 1] += xv * wv.y;
                acc[4 * j + 2] += xv * wv.z;
                acc[4 * j + 3] += xv * wv.w;
            }
        }
    }

    if (row < n) {
        float es = 0.0f, ed = 0.0f;
#pragma unroll
        for (int j = 0; j < OUT_CH; j++) {
            es += acc[j] * as[j];
            ed += acc[j] * as[OUT_CH + j];
        }
        g_es[row] = es;
        g_ed[row] = ed;
        float4* dst = reinterpret_cast<float4*>(&g_wh[(size_t)row * OUT_CH]);
#pragma unroll
        for (int j = 0; j < 16; j++)
            dst[j] = make_float4(acc[4 * j], acc[4 * j + 1], acc[4 * j + 2], acc[4 * j + 3]);
    }
}

// ---------------- kernel 2: decode indices + per-edge score + global max ----
// leaky_relu(v) > 0  <=>  v > 0, and where() replaces the <=0 branch entirely,
// so score = (v > 0) ? v : NEG_BIG.
__global__ void score_max_kernel(const void* __restrict__ ei_raw, int nE) {
    const int is64 = g_is64;
    const int*       ei32 = (const int*)ei_raw;
    const long long* ei64 = (const long long*)ei_raw;
    float local = NEG_BIG;
    for (int e = blockIdx.x * blockDim.x + threadIdx.x; e < nE;
         e += gridDim.x * blockDim.x) {
        int src, dst;
        if (is64) { src = (int)ei64[e]; dst = (int)ei64[nE + e]; }
        else      { src =      ei32[e]; dst =      ei32[nE + e]; }
        g_src[e] = src;
        g_dst[e] = dst;
        float v = g_es[src] + g_ed[dst];
        float s = (v > 0.0f) ? v : NEG_BIG;
        g_s[e] = s;
        local = fmaxf(local, s);
    }
#pragma unroll
    for (int o = 16; o > 0; o >>= 1)
        local = fmaxf(local, __shfl_xor_sync(0xFFFFFFFFu, local, o));
    // int atomicMax is order-preserving for positive floats; only positive
    // candidates matter (g_max pre-set to NEG_BIG).
    if ((threadIdx.x & 31) == 0 && local > 0.0f)
        atomicMax(reinterpret_cast<int*>(&g_max), __float_as_int(local));
}

// ---------------- kernel 3: sum of exp; store exp(s-max) back into g_s ----
__global__ void sumexp_kernel(int nE) {
    const float m = g_max;
    float local = 0.0f;
    for (int e = blockIdx.x * blockDim.x + threadIdx.x; e < nE;
         e += gridDim.x * blockDim.x) {
        float ex = expf(g_s[e] - m);   // NEG_BIG - m underflows to exactly 0
        g_s[e] = ex;
        local += ex;
    }
#pragma unroll
    for (int o = 16; o > 0; o >>= 1)
        local += __shfl_xor_sync(0xFFFFFFFFu, local, o);
    if ((threadIdx.x & 31) == 0) atomicAdd(&g_sum, local);
}

// ---------------- kernel 4: weighted scatter via v4 reductions ----------
// 16 threads per edge, one float4 each (64 features).
__global__ void scatter_kernel(float* __restrict__ out, int nE) {
    int gt = blockIdx.x * blockDim.x + threadIdx.x;
    int e = gt >> 4;
    int t = gt & 15;
    if (e >= nE) return;
    int src = g_src[e];
    int dst = g_dst[e];
    float w = g_s[e] * (1.0f / g_sum);
    float4 v = *reinterpret_cast<const float4*>(&g_wh[(size_t)src * OUT_CH + t * 4]);
    float* o = &out[(size_t)dst * OUT_CH + t * 4];
    asm volatile("red.global.add.v4.f32 [%0], {%1, %2, %3, %4};"
                 :: "l"(o), "f"(w * v.x), "f"(w * v.y), "f"(w * v.z), "f"(w * v.w)
                 : "memory");
}

// ---------------- kernel 5: in-place ELU ----------------
__global__ void elu_kernel(float* __restrict__ out, int total) {
    int i = blockIdx.x * blockDim.x + threadIdx.x;
    if (i >= total) return;
    float v = out[i];
    out[i] = (v > 0.0f) ? v : expm1f(v);
}

// ---------------- launch ----------------
extern "C" void kernel_launch(void* const* d_in, const int* in_sizes, int n_in,
                              void* d_out, int out_size) {
    const float* x   = (const float*)d_in[0];
    const void*  ei  = d_in[1];
    const float* W   = (const float*)d_in[2];
    const float* a   = (const float*)d_in[3];
    float*       out = (float*)d_out;

    int n  = in_sizes[0] / IN_CH;   // 50000
    int nE = in_sizes[1] / 2;       // 800000
    int total = n * OUT_CH;

    detect_kernel<<<1, 32>>>((const unsigned int*)ei);
    init_kernel<<<1024, 256>>>(out, total);
    gemm_kernel<<<(n + 127) / 128, 128>>>(x, W, a, n);
    score_max_kernel<<<2048, 256>>>(ei, nE);
    sumexp_kernel<<<2048, 256>>>(nE);
    {
        long long threads = (long long)nE * 16;
        int blocks = (int)((threads + 255) / 256);
        scatter_kernel<<<blocks, 256>>>(out, nE);
    }
    elu_kernel<<<(total + 255) / 256, 256>>>(out, total);
}

// round 4
// speedup vs baseline: 1.2810x; 1.2810x over previous
#include <cuda_runtime.h>
#include <cuda_bf16.h>
#include <math_constants.h>

#define N_NODES_MAX 50000
#define N_EDGES_MAX 800000
#define IN_CH 256
#define OUT_CH 64
#define NEG_BIG -9e15f

// ---------------- scratch (device globals: allocation-free) ----------------
__device__ float g_wh[(size_t)N_NODES_MAX * OUT_CH];   // 12.8 MB
__device__ float g_es[N_NODES_MAX];                    // e_src per node
__device__ float g_ed[N_NODES_MAX];                    // e_dst per node
__device__ int2  g_sd[N_EDGES_MAX];                    // compacted (src,dst)
__device__ float g_w[N_EDGES_MAX];                     // compacted exp(v - M)
__device__ float g_maxs;                               // max over e_src
__device__ float g_maxd;                               // max over e_dst
__device__ float g_sum;                                // sum of exp(v - M)
__device__ int   g_cnt;                                // surviving edge count
__device__ int   g_is64;

// float atomic max valid for mixed signs (init to -inf)
__device__ __forceinline__ void atomicMaxF(float* addr, float v) {
    if (v >= 0.0f) atomicMax((int*)addr, __float_as_int(v));
    else           atomicMin((unsigned int*)addr, __float_as_uint(v));
}

__device__ __forceinline__ void ffma2(unsigned long long& acc,
                                      unsigned long long a,
                                      unsigned long long b) {
    asm("fma.rn.f32x2 %0, %1, %2, %0;" : "+l"(acc) : "l"(a), "l"(b));
}

// ---------------- kernel A: detect edge-index dtype ----------------
// int64 indices < 2^31 have all-zero high words; genuine int32 data has random
// values at odd word positions (P[256 zeros] ~ 0).
__global__ void detect_kernel(const unsigned int* __restrict__ ei_w) {
    if (threadIdx.x == 0) {
        unsigned int any = 0;
        for (int i = 1; i < 256; i += 2) any |= ei_w[i];
        g_is64 = (any == 0) ? 1 : 0;
    }
}

// ---------------- kernel 0: init output + scalars ----------------
__global__ void init_kernel(float* __restrict__ out, int total) {
    int gtid = blockIdx.x * blockDim.x + threadIdx.x;
    if (gtid == 0) {
        g_maxs = -CUDART_INF_F;
        g_maxd = -CUDART_INF_F;
        g_sum = 0.0f;
        g_cnt = 0;
    }
    float4* o4 = (float4*)out;
    for (int i = gtid; i < total / 4; i += gridDim.x * blockDim.x)
        o4[i] = make_float4(0.f, 0.f, 0.f, 0.f);
}

// ---------------- kernel 1: wh = x@W (f32x2 packed), e_src/e_dst, maxes ----
// 128 threads/block, one node row per thread, 64 outputs in 32 packed regs.
__global__ __launch_bounds__(128) void gemm_kernel(
    const float* __restrict__ x, const float* __restrict__ W,
    const float* __restrict__ a, int n)
{
    __shared__ float xs[128][33];     // (tid*33+k)%32 = (tid+k)%32: conflict-free
    __shared__ float ws[32][64];      // 256B rows, 16B-aligned
    __shared__ float as[2 * OUT_CH];

    const int tid  = threadIdx.x;
    const int row0 = blockIdx.x * 128;
    const int row  = row0 + tid;

    as[tid] = a[tid];

    unsigned long long acc2[32];      // packed f32x2, {out2j, out2j+1}
#pragma unroll
    for (int j = 0; j < 32; j++) acc2[j] = 0ull;

    for (int kc = 0; kc < IN_CH; kc += 32) {
        __syncthreads();
#pragma unroll
        for (int i = 0; i < 32; i++) {            // x tile 128x32, coalesced
            int idx = i * 128 + tid;
            int r = idx >> 5, c = idx & 31;
            int gr = row0 + r;
            xs[r][c] = (gr < n) ? x[(size_t)gr * IN_CH + kc + c] : 0.0f;
        }
#pragma unroll
        for (int i = 0; i < 16; i++) {            // W tile 32x64, coalesced
            int idx = i * 128 + tid;
            int r = idx >> 6, c = idx & 63;
            ws[r][c] = W[(size_t)(kc + r) * OUT_CH + c];
        }
        __syncthreads();

#pragma unroll
        for (int k = 0; k < 32; k++) {
            float xv = xs[tid][k];
            unsigned long long x2;
            asm("mov.b64 %0, {%1, %2};" : "=l"(x2) : "f"(xv), "f"(xv));
            const ulonglong2* wq = reinterpret_cast<const ulonglong2*>(ws[k]);
#pragma unroll
            for (int jj = 0; jj < 16; jj++) {     // warp-uniform LDS.128 bcast
                ulonglong2 q = wq[jj];
                ffma2(acc2[2 * jj + 0], x2, q.x);
                ffma2(acc2[2 * jj + 1], x2, q.y);
            }
        }
    }

    // epilogue: unpack, e_src/e_dst dots, store, block maxes
    float es = -CUDART_INF_F, ed = -CUDART_INF_F;
    if (row < n) {
        float accv[OUT_CH];
#pragma unroll
        for (int j = 0; j < 32; j++) {
            float lo, hi;
            asm("mov.b64 {%0, %1}, %2;" : "=f"(lo), "=f"(hi) : "l"(acc2[j]));
            accv[2 * j] = lo; accv[2 * j + 1] = hi;
        }
        es = 0.0f; ed = 0.0f;
#pragma unroll
        for (int j = 0; j < OUT_CH; j++) {
            es += accv[j] * as[j];
            ed += accv[j] * as[OUT_CH + j];
        }
        g_es[row] = es;
        g_ed[row] = ed;
        float4* dst = reinterpret_cast<float4*>(&g_wh[(size_t)row * OUT_CH]);
#pragma unroll
        for (int j = 0; j < 16; j++)
            dst[j] = make_float4(accv[4 * j], accv[4 * j + 1],
                                 accv[4 * j + 2], accv[4 * j + 3]);
    }
    float ms = es, md = ed;
#pragma unroll
    for (int o = 16; o > 0; o >>= 1) {
        ms = fmaxf(ms, __shfl_xor_sync(0xFFFFFFFFu, ms, o));
        md = fmaxf(md, __shfl_xor_sync(0xFFFFFFFFu, md, o));
    }
    if ((tid & 31) == 0) {
        atomicMaxF(&g_maxs, ms);
        atomicMaxF(&g_maxd, md);
    }
}

// ---------------- kernel 2: decode + mask + exp + compact + sum ----------
// leaky_relu(v)>0 <=> v>0; masked edges get weight exp(NEG_BIG - max) == 0.0
// exactly, so dropping them is bit-identical for the segment sum. Any upper
// bound M >= true max yields an identical softmax (ratios invariant), and
// M = max(e_src)+max(e_dst) >= max(e_src[s]+e_dst[d]).
__global__ void compact_kernel(const void* __restrict__ ei_raw, int nE) {
    const int gt = blockIdx.x * blockDim.x + threadIdx.x;
    const int lane = threadIdx.x & 31;
    const int is64 = g_is64;
    const float M = g_maxs + g_maxd;

    int src = 0, dst = 0;
    float v = -1.0f;
    if (gt < nE) {
        if (is64) {
            src = (int)((const long long*)ei_raw)[gt];
            dst = (int)((const long long*)ei_raw)[nE + gt];
        } else {
            src = ((const int*)ei_raw)[gt];
            dst = ((const int*)ei_raw)[nE + gt];
        }
        v = g_es[src] + g_ed[dst];
    }
    bool keep = v > 0.0f;
    unsigned bal = __ballot_sync(0xFFFFFFFFu, keep);
    float ex = keep ? expf(v - M) : 0.0f;

    if (bal) {
        int leader = __ffs(bal) - 1;
        int rank = __popc(bal & ((1u << lane) - 1u));
        int base = 0;
        if (lane == leader) base = atomicAdd(&g_cnt, __popc(bal));
        base = __shfl_sync(0xFFFFFFFFu, base, leader);
        if (keep) {
            g_sd[base + rank] = make_int2(src, dst);
            g_w[base + rank] = ex;
        }
    }
    // warp-reduced sum of exp
#pragma unroll
    for (int o = 16; o > 0; o >>= 1)
        ex += __shfl_xor_sync(0xFFFFFFFFu, ex, o);
    if (lane == 0 && ex > 0.0f) atomicAdd(&g_sum, ex);
}

// ---------------- kernel 3: weighted scatter (survivors only) ----------
// 16 threads per edge, one float4 each; unnormalized (1/sum applied in elu).
__global__ void scatter_kernel(float* __restrict__ out) {
    int gt = blockIdx.x * blockDim.x + threadIdx.x;
    int e = gt >> 4;
    if (e >= g_cnt) return;
    int t = gt & 15;
    int2 sd = g_sd[e];
    float w = g_w[e];
    float4 v = *reinterpret_cast<const float4*>(
        &g_wh[(size_t)sd.x * OUT_CH + t * 4]);
    float* o = &out[(size_t)sd.y * OUT_CH + t * 4];
    asm volatile("red.global.add.v4.f32 [%0], {%1, %2, %3, %4};"
                 :: "l"(o), "f"(w * v.x), "f"(w * v.y), "f"(w * v.z), "f"(w * v.w)
                 : "memory");
}

// ---------------- kernel 4: normalize + ELU in place ----------------
__global__ void elu_kernel(float* __restrict__ out, int total) {
    int i = blockIdx.x * blockDim.x + threadIdx.x;
    if (i >= total / 4) return;
    float S = g_sum;
    float inv = (S > 0.0f) ? (1.0f / S) : 0.0f;
    float4 v = reinterpret_cast<float4*>(out)[i];
    v.x *= inv; v.y *= inv; v.z *= inv; v.w *= inv;
    v.x = (v.x > 0.0f) ? v.x : expm1f(v.x);
    v.y = (v.y > 0.0f) ? v.y : expm1f(v.y);
    v.z = (v.z > 0.0f) ? v.z : expm1f(v.z);
    v.w = (v.w > 0.0f) ? v.w : expm1f(v.w);
    reinterpret_cast<float4*>(out)[i] = v;
}

// ---------------- launch ----------------
extern "C" void kernel_launch(void* const* d_in, const int* in_sizes, int n_in,
                              void* d_out, int out_size) {
    const float* x   = (const float*)d_in[0];
    const void*  ei  = d_in[1];
    const float* W   = (const float*)d_in[2];
    const float* a   = (const float*)d_in[3];
    float*       out = (float*)d_out;

    int n  = in_sizes[0] / IN_CH;   // 50000
    int nE = in_sizes[1] / 2;       // 800000
    int total = n * OUT_CH;

    detect_kernel<<<1, 32>>>((const unsigned int*)ei);
    init_kernel<<<512, 256>>>(out, total);
    gemm_kernel<<<(n + 127) / 128, 128>>>(x, W, a, n);
    compact_kernel<<<(nE + 255) / 256, 256>>>(ei, nE);
    {
        long long threads = (long long)nE * 16;   // worst case: all survive
        int blocks = (int)((threads + 255) / 256);
        scatter_kernel<<<blocks, 256>>>(out);
    }
    elu_kernel<<<(total / 4 + 255) / 256, 256>>>(out, total);
}

// round 5
// speedup vs baseline: 1.3862x; 1.0821x over previous
#include <cuda_runtime.h>
#include <cuda_bf16.h>
#include <math_constants.h>

#define N_NODES_MAX 50000
#define N_EDGES_MAX 800000
#define IN_CH 256
#define OUT_CH 64

// ---------------- scratch (device globals: allocation-free) ----------------
__device__ float g_wh[(size_t)N_NODES_MAX * OUT_CH];   // 12.8 MB
__device__ float g_es[N_NODES_MAX];                    // e_src per node
__device__ float g_ed[N_NODES_MAX];                    // e_dst per node
__device__ float g_maxs;                               // max over e_src
__device__ float g_maxd;                               // max over e_dst
__device__ float g_sum;                                // sum of exp(v - M)
__device__ int   g_is64;

// float atomic max valid for mixed signs (init to -inf)
__device__ __forceinline__ void atomicMaxF(float* addr, float v) {
    if (v >= 0.0f) atomicMax((int*)addr, __float_as_int(v));
    else           atomicMin((unsigned int*)addr, __float_as_uint(v));
}

__device__ __forceinline__ void ffma2(unsigned long long& acc,
                                      unsigned long long a,
                                      unsigned long long b) {
    asm("fma.rn.f32x2 %0, %1, %2, %0;" : "+l"(acc) : "l"(a), "l"(b));
}

// ---------------- kernel A: detect edge-index dtype ----------------
// int64 indices < 2^31 have all-zero high words; genuine int32 data has random
// values at odd word positions (P[256 zeros] ~ 0).
__global__ void detect_kernel(const unsigned int* __restrict__ ei_w) {
    if (threadIdx.x == 0) {
        unsigned int any = 0;
        for (int i = 1; i < 256; i += 2) any |= ei_w[i];
        g_is64 = (any == 0) ? 1 : 0;
    }
}

// ---------------- kernel 0: init output + scalars ----------------
__global__ void init_kernel(float* __restrict__ out, int total) {
    int gtid = blockIdx.x * blockDim.x + threadIdx.x;
    if (gtid == 0) {
        g_maxs = -CUDART_INF_F;
        g_maxd = -CUDART_INF_F;
        g_sum = 0.0f;
    }
    float4* o4 = (float4*)out;
    for (int i = gtid; i < total / 4; i += gridDim.x * blockDim.x)
        o4[i] = make_float4(0.f, 0.f, 0.f, 0.f);
}

// ---------------- kernel 1: wh = x@W (f32x2 packed), e_src/e_dst, maxes ----
// 128 threads/block, one node row per thread, 64 outputs in 32 packed regs.
__global__ __launch_bounds__(128) void gemm_kernel(
    const float* __restrict__ x, const float* __restrict__ W,
    const float* __restrict__ a, int n)
{
    __shared__ float xs[128][33];     // conflict-free xs[tid][k]
    __shared__ float ws[32][64];      // 256B rows, 16B-aligned
    __shared__ float as_[2 * OUT_CH];

    const int tid  = threadIdx.x;
    const int row0 = blockIdx.x * 128;
    const int row  = row0 + tid;

    as_[tid] = a[tid];

    unsigned long long acc2[32];      // packed f32x2: {out2j, out2j+1}
#pragma unroll
    for (int j = 0; j < 32; j++) acc2[j] = 0ull;

    for (int kc = 0; kc < IN_CH; kc += 32) {
        __syncthreads();
#pragma unroll
        for (int i = 0; i < 32; i++) {            // x tile 128x32, coalesced
            int idx = i * 128 + tid;
            int r = idx >> 5, c = idx & 31;
            int gr = row0 + r;
            xs[r][c] = (gr < n) ? x[(size_t)gr * IN_CH + kc + c] : 0.0f;
        }
#pragma unroll
        for (int i = 0; i < 16; i++) {            // W tile 32x64, coalesced
            int idx = i * 128 + tid;
            int r = idx >> 6, c = idx & 63;
            ws[r][c] = W[(size_t)(kc + r) * OUT_CH + c];
        }
        __syncthreads();

#pragma unroll
        for (int k = 0; k < 32; k++) {
            float xv = xs[tid][k];
            unsigned long long x2;
            asm("mov.b64 %0, {%1, %2};" : "=l"(x2) : "f"(xv), "f"(xv));
            const ulonglong2* wq = reinterpret_cast<const ulonglong2*>(ws[k]);
#pragma unroll
            for (int jj = 0; jj < 16; jj++) {     // warp-uniform LDS.128 bcast
                ulonglong2 q = wq[jj];
                ffma2(acc2[2 * jj + 0], x2, q.x);
                ffma2(acc2[2 * jj + 1], x2, q.y);
            }
        }
    }

    // epilogue: stream-unpack pairs (no 64-reg temp array -> no spills)
    float es = -CUDART_INF_F, ed = -CUDART_INF_F;
    if (row < n) {
        es = 0.0f; ed = 0.0f;
        float2* dst2 = reinterpret_cast<float2*>(&g_wh[(size_t)row * OUT_CH]);
#pragma unroll
        for (int j = 0; j < 32; j++) {
            float lo, hi;
            asm("mov.b64 {%0, %1}, %2;" : "=f"(lo), "=f"(hi) : "l"(acc2[j]));
            es += lo * as_[2 * j]          + hi * as_[2 * j + 1];
            ed += lo * as_[OUT_CH + 2 * j] + hi * as_[OUT_CH + 2 * j + 1];
            dst2[j] = make_float2(lo, hi);
        }
        g_es[row] = es;
        g_ed[row] = ed;
    }
    float ms = es, md = ed;
#pragma unroll
    for (int o = 16; o > 0; o >>= 1) {
        ms = fmaxf(ms, __shfl_xor_sync(0xFFFFFFFFu, ms, o));
        md = fmaxf(md, __shfl_xor_sync(0xFFFFFFFFu, md, o));
    }
    if ((tid & 31) == 0) {
        atomicMaxF(&g_maxs, ms);
        atomicMaxF(&g_maxd, md);
    }
}

// ---------------- kernel 2: FUSED edge pass ----------------
// score + mask + exp + weighted scatter + sum, no intermediates.
// Each warp takes 32 edges: lane i owns edge base+i (batched independent
// gathers -> high MLP), then iterates the surviving lanes two-at-a-time
// (16 lanes per edge, float4 gather + red.global.add.v4).
// leaky_relu(v)>0 <=> v>0; masked edges have weight exp(NEG_BIG-M) == +0.0
// exactly, so skipping them is bit-identical. M = max(es)+max(ed) >= true max
// is a valid softmax shift (ratios invariant).
__global__ void edge_kernel(const void* __restrict__ ei_raw,
                            float* __restrict__ out, int nE) {
    const int lane   = threadIdx.x & 31;
    const int warpId = (blockIdx.x * blockDim.x + threadIdx.x) >> 5;
    const int nWarps = (gridDim.x * blockDim.x) >> 5;
    const int is64   = g_is64;
    const float M    = g_maxs + g_maxd;
    const int half   = lane >> 4;          // 0: first edge, 1: second edge
    const int t      = lane & 15;          // feature quarter-row

    float sumacc = 0.0f;

    for (int base = warpId * 32; base < nE; base += nWarps * 32) {
        int e = base + lane;
        int src = 0, dst = 0;
        float v = -1.0f;
        if (e < nE) {
            if (is64) {
                src = (int)((const long long*)ei_raw)[e];
                dst = (int)((const long long*)ei_raw)[nE + e];
            } else {
                src = ((const int*)ei_raw)[e];
                dst = ((const int*)ei_raw)[nE + e];
            }
            v = g_es[src] + g_ed[dst];
        }
        bool keep = v > 0.0f;
        unsigned mask = __ballot_sync(0xFFFFFFFFu, keep);
        float w = keep ? expf(v - M) : 0.0f;
        sumacc += w;

        while (mask) {
            int l0 = __ffs(mask) - 1; mask &= mask - 1;
            int l1 = -1;
            if (mask) { l1 = __ffs(mask) - 1; mask &= mask - 1; }
            int sl = half ? l1 : l0;
            // warp-uniform loop; shfl from fixed lanes, all lanes present
            float ws = __shfl_sync(0xFFFFFFFFu, w,   sl < 0 ? 0 : sl);
            int   ss = __shfl_sync(0xFFFFFFFFu, src, sl < 0 ? 0 : sl);
            int   ds = __shfl_sync(0xFFFFFFFFu, dst, sl < 0 ? 0 : sl);
            if (sl >= 0) {
                float4 vv = *reinterpret_cast<const float4*>(
                    &g_wh[(size_t)ss * OUT_CH + t * 4]);
                float* o = &out[(size_t)ds * OUT_CH + t * 4];
                asm volatile("red.global.add.v4.f32 [%0], {%1, %2, %3, %4};"
                             :: "l"(o), "f"(ws * vv.x), "f"(ws * vv.y),
                                "f"(ws * vv.z), "f"(ws * vv.w)
                             : "memory");
            }
        }
    }

#pragma unroll
    for (int o = 16; o > 0; o >>= 1)
        sumacc += __shfl_xor_sync(0xFFFFFFFFu, sumacc, o);
    if (lane == 0 && sumacc > 0.0f) atomicAdd(&g_sum, sumacc);
}

// ---------------- kernel 3: normalize + ELU in place ----------------
__global__ void elu_kernel(float* __restrict__ out, int total) {
    int i = blockIdx.x * blockDim.x + threadIdx.x;
    if (i >= total / 4) return;
    float S = g_sum;
    float inv = (S > 0.0f) ? (1.0f / S) : 0.0f;
    float4 v = reinterpret_cast<float4*>(out)[i];
    v.x *= inv; v.y *= inv; v.z *= inv; v.w *= inv;
    v.x = (v.x > 0.0f) ? v.x : expm1f(v.x);
    v.y = (v.y > 0.0f) ? v.y : expm1f(v.y);
    v.z = (v.z > 0.0f) ? v.z : expm1f(v.z);
    v.w = (v.w > 0.0f) ? v.w : expm1f(v.w);
    reinterpret_cast<float4*>(out)[i] = v;
}

// ---------------- launch ----------------
extern "C" void kernel_launch(void* const* d_in, const int* in_sizes, int n_in,
                              void* d_out, int out_size) {
    const float* x   = (const float*)d_in[0];
    const void*  ei  = d_in[1];
    const float* W   = (const float*)d_in[2];
    const float* a   = (const float*)d_in[3];
    float*       out = (float*)d_out;

    int n  = in_sizes[0] / IN_CH;   // 50000
    int nE = in_sizes[1] / 2;       // 800000
    int total = n * OUT_CH;

    detect_kernel<<<1, 32>>>((const unsigned int*)ei);
    init_kernel<<<512, 256>>>(out, total);
    gemm_kernel<<<(n + 127) / 128, 128>>>(x, W, a, n);
    edge_kernel<<<1184, 256>>>(ei, out, nE);   // 8 blocks/SM x 148
    elu_kernel<<<(total / 4 + 255) / 256, 256>>>(out, total);
}

// round 9
// speedup vs baseline: 2.0270x; 1.4623x over previous
#include <cuda_runtime.h>
#include <cuda_bf16.h>
#include <math_constants.h>
#include <cstdint>

#define N_NODES_MAX 50000
#define N_EDGES_MAX 800000
#define IN_CH 256
#define OUT_CH 64

// ---------------- scratch (device globals: allocation-free) ----------------
__device__ float g_wh[(size_t)N_NODES_MAX * OUT_CH];   // 12.8 MB
__device__ float g_es[N_NODES_MAX];
__device__ float g_ed[N_NODES_MAX];
__device__ float g_wf[32][8][32][4];                   // B frags: [ks][nb][lane]{bh0,bh1,bl0,bl1}
__device__ float g_maxs;
__device__ float g_maxd;
__device__ float g_sum;
__device__ int   g_is64;

// ---------------- helpers ----------------
__device__ __forceinline__ void atomicMaxF(float* addr, float v) {
    if (v >= 0.0f) atomicMax((int*)addr, __float_as_int(v));
    else           atomicMin((unsigned int*)addr, __float_as_uint(v));
}

__device__ __forceinline__ float tf32_round(float v) {
    uint32_t u;
    asm("cvt.rna.tf32.f32 %0, %1;" : "=r"(u) : "f"(v));
    return __uint_as_float(u);
}

// D += A(16x8,row) * B(8x8,col) in tf32, fp32 accum
__device__ __forceinline__ void mma_tf32(float* c, const uint32_t* a,
                                         uint32_t b0, uint32_t b1) {
    asm volatile(
        "mma.sync.aligned.m16n8k8.row.col.f32.tf32.tf32.f32 "
        "{%0,%1,%2,%3}, {%4,%5,%6,%7}, {%8,%9}, {%0,%1,%2,%3};"
        : "+f"(c[0]), "+f"(c[1]), "+f"(c[2]), "+f"(c[3])
        : "r"(a[0]), "r"(a[1]), "r"(a[2]), "r"(a[3]), "r"(b0), "r"(b1));
}

// ---------------- kernel A: detect edge-index dtype ----------------
// int64 indices < 2^31 have all-zero high words; genuine int32 data has random
// values at odd word positions (P[256 zeros] ~ 0).
__global__ void detect_kernel(const unsigned int* __restrict__ ei_w) {
    if (threadIdx.x == 0) {
        unsigned int any = 0;
        for (int i = 1; i < 256; i += 2) any |= ei_w[i];
        g_is64 = (any == 0) ? 1 : 0;
    }
}

// ---------------- kernel 0: init output + scalars ----------------
__global__ void init_kernel(float* __restrict__ out, int total) {
    int gtid = blockIdx.x * blockDim.x + threadIdx.x;
    if (gtid == 0) {
        g_maxs = -CUDART_INF_F;
        g_maxd = -CUDART_INF_F;
        g_sum = 0.0f;
    }
    float4* o4 = (float4*)out;
    for (int i = gtid; i < total / 4; i += gridDim.x * blockDim.x)
        o4[i] = make_float4(0.f, 0.f, 0.f, 0.f);
}

// ---------------- kernel W: pack W into per-lane tf32 hi/lo B fragments ----
// For m16n8k8 col-major B: lane(gid,tig) holds b0=B[k=tig][n=gid],
// b1=B[k=tig+4][n=gid] within each 8x8 block.
__global__ void wprep_kernel(const float* __restrict__ W) {
    int idx = blockIdx.x * blockDim.x + threadIdx.x;
    if (idx >= 32 * 8 * 32) return;
    int lane = idx & 31, nb = (idx >> 5) & 7, ks = idx >> 8;
    int tig = lane & 3, gid = lane >> 2;
    int k0 = ks * 8 + tig, nn = nb * 8 + gid;
    float w0 = W[(size_t)k0 * OUT_CH + nn];
    float w1 = W[(size_t)(k0 + 4) * OUT_CH + nn];
    float h0 = tf32_round(w0), h1 = tf32_round(w1);
    float l0 = tf32_round(w0 - h0), l1 = tf32_round(w1 - h1);
    *(float4*)&g_wf[ks][nb][lane][0] = make_float4(h0, h1, l0, l1);
}

// ---------------- kernel 1: 3xTF32 mma.sync GEMM + attention epilogue ----
// 8 warps/CTA, each warp: 16 rows x 64 cols, K=256 in 32 steps of 8.
__global__ __launch_bounds__(256) void gemm_mma_kernel(
    const float* __restrict__ x, const float* __restrict__ a, int n)
{
    __shared__ float as_[2 * OUT_CH];
    const int tid = threadIdx.x, wid = tid >> 5, lane = tid & 31;
    const int gid = lane >> 2, tig = lane & 3;
    if (tid < 128) as_[tid] = a[tid];
    __syncthreads();

    const int r0 = blockIdx.x * 128 + wid * 16 + gid;
    const int r8 = r0 + 8;
    const bool v0 = r0 < n, v8 = r8 < n;
    const float* p0 = x + (size_t)r0 * IN_CH + tig;
    const float* p8 = x + (size_t)r8 * IN_CH + tig;

    float acc[8][4];
#pragma unroll
    for (int nb = 0; nb < 8; nb++)
#pragma unroll
        for (int j = 0; j < 4; j++) acc[nb][j] = 0.0f;

#pragma unroll 4
    for (int ks = 0; ks < 32; ks++) {
        const int kc = ks * 8;
        // A fragment: a0=(r0,k), a1=(r8,k), a2=(r0,k+4), a3=(r8,k+4)
        float x0 = v0 ? __ldg(p0 + kc)     : 0.0f;
        float x1 = v8 ? __ldg(p8 + kc)     : 0.0f;
        float x2 = v0 ? __ldg(p0 + kc + 4) : 0.0f;
        float x3 = v8 ? __ldg(p8 + kc + 4) : 0.0f;
        uint32_t ah[4], al[4];
        float h;
        h = tf32_round(x0); ah[0] = __float_as_uint(h); al[0] = __float_as_uint(tf32_round(x0 - h));
        h = tf32_round(x1); ah[1] = __float_as_uint(h); al[1] = __float_as_uint(tf32_round(x1 - h));
        h = tf32_round(x2); ah[2] = __float_as_uint(h); al[2] = __float_as_uint(tf32_round(x2 - h));
        h = tf32_round(x3); ah[3] = __float_as_uint(h); al[3] = __float_as_uint(tf32_round(x3 - h));

#pragma unroll
        for (int nb = 0; nb < 8; nb++) {
            float4 f = __ldg((const float4*)&g_wf[ks][nb][lane][0]);
            uint32_t bh0 = __float_as_uint(f.x), bh1 = __float_as_uint(f.y);
            uint32_t bl0 = __float_as_uint(f.z), bl1 = __float_as_uint(f.w);
            mma_tf32(acc[nb], ah, bh0, bh1);   // hi*hi
            mma_tf32(acc[nb], ah, bl0, bl1);   // hi*lo
            mma_tf32(acc[nb], al, bh0, bh1);   // lo*hi
        }
    }

    // ---- epilogue: wh stores + es/ed dots + maxes ----
    float es0 = 0.f, ed0 = 0.f, es8 = 0.f, ed8 = 0.f;
#pragma unroll
    for (int nb = 0; nb < 8; nb++) {
        int c0 = nb * 8 + 2 * tig;
        es0 += acc[nb][0] * as_[c0] + acc[nb][1] * as_[c0 + 1];
        ed0 += acc[nb][0] * as_[OUT_CH + c0] + acc[nb][1] * as_[OUT_CH + c0 + 1];
        es8 += acc[nb][2] * as_[c0] + acc[nb][3] * as_[c0 + 1];
        ed8 += acc[nb][2] * as_[OUT_CH + c0] + acc[nb][3] * as_[OUT_CH + c0 + 1];
        if (v0) *(float2*)&g_wh[(size_t)r0 * OUT_CH + c0] =
            make_float2(acc[nb][0], acc[nb][1]);
        if (v8) *(float2*)&g_wh[(size_t)r8 * OUT_CH + c0] =
            make_float2(acc[nb][2], acc[nb][3]);
    }
    // reduce across the 4 lanes of each quad (same row)
#pragma unroll
    for (int o = 1; o <= 2; o <<= 1) {
        es0 += __shfl_xor_sync(0xFFFFFFFFu, es0, o);
        ed0 += __shfl_xor_sync(0xFFFFFFFFu, ed0, o);
        es8 += __shfl_xor_sync(0xFFFFFFFFu, es8, o);
        ed8 += __shfl_xor_sync(0xFFFFFFFFu, ed8, o);
    }
    if (tig == 0 && v0) { g_es[r0] = es0; g_ed[r0] = ed0; }
    if (tig == 0 && v8) { g_es[r8] = es8; g_ed[r8] = ed8; }

    float ms = fmaxf(v0 ? es0 : -CUDART_INF_F, v8 ? es8 : -CUDART_INF_F);
    float md = fmaxf(v0 ? ed0 : -CUDART_INF_F, v8 ? ed8 : -CUDART_INF_F);
#pragma unroll
    for (int o = 16; o > 0; o >>= 1) {
        ms = fmaxf(ms, __shfl_xor_sync(0xFFFFFFFFu, ms, o));
        md = fmaxf(md, __shfl_xor_sync(0xFFFFFFFFu, md, o));
    }
    if (lane == 0) {
        atomicMaxF(&g_maxs, ms);
        atomicMaxF(&g_maxd, md);
    }
}

// ---------------- kernel 2: FUSED edge pass (unchanged) ----------------
// score + mask + exp + weighted scatter + sum; masked edges have weight
// exp(NEG_BIG-M) == +0.0 exactly, so skipping them is bit-identical.
// M = max(es)+max(ed) >= true max: valid softmax shift.
__global__ void edge_kernel(const void* __restrict__ ei_raw,
                            float* __restrict__ out, int nE) {
    const int lane   = threadIdx.x & 31;
    const int warpId = (blockIdx.x * blockDim.x + threadIdx.x) >> 5;
    const int nWarps = (gridDim.x * blockDim.x) >> 5;
    const int is64   = g_is64;
    const float M    = g_maxs + g_maxd;
    const int half   = lane >> 4;
    const int t      = lane & 15;

    float sumacc = 0.0f;

    for (int base = warpId * 32; base < nE; base += nWarps * 32) {
        int e = base + lane;
        int src = 0, dst = 0;
        float v = -1.0f;
        if (e < nE) {
            if (is64) {
                src = (int)((const long long*)ei_raw)[e];
                dst = (int)((const long long*)ei_raw)[nE + e];
            } else {
                src = ((const int*)ei_raw)[e];
                dst = ((const int*)ei_raw)[nE + e];
            }
            v = g_es[src] + g_ed[dst];
        }
        bool keep = v > 0.0f;
        unsigned mask = __ballot_sync(0xFFFFFFFFu, keep);
        float w = keep ? expf(v - M) : 0.0f;
        sumacc += w;

        while (mask) {
            int l0 = __ffs(mask) - 1; mask &= mask - 1;
            int l1 = -1;
            if (mask) { l1 = __ffs(mask) - 1; mask &= mask - 1; }
            int sl = half ? l1 : l0;
            float ws = __shfl_sync(0xFFFFFFFFu, w,   sl < 0 ? 0 : sl);
            int   ss = __shfl_sync(0xFFFFFFFFu, src, sl < 0 ? 0 : sl);
            int   ds = __shfl_sync(0xFFFFFFFFu, dst, sl < 0 ? 0 : sl);
            if (sl >= 0) {
                float4 vv = *reinterpret_cast<const float4*>(
                    &g_wh[(size_t)ss * OUT_CH + t * 4]);
                float* o = &out[(size_t)ds * OUT_CH + t * 4];
                asm volatile("red.global.add.v4.f32 [%0], {%1, %2, %3, %4};"
                             :: "l"(o), "f"(ws * vv.x), "f"(ws * vv.y),
                                "f"(ws * vv.z), "f"(ws * vv.w)
                             : "memory");
            }
        }
    }

#pragma unroll
    for (int o = 16; o > 0; o >>= 1)
        sumacc += __shfl_xor_sync(0xFFFFFFFFu, sumacc, o);
    if (lane == 0 && sumacc > 0.0f) atomicAdd(&g_sum, sumacc);
}

// ---------------- kernel 3: normalize + ELU in place ----------------
__global__ void elu_kernel(float* __restrict__ out, int total) {
    int i = blockIdx.x * blockDim.x + threadIdx.x;
    if (i >= total / 4) return;
    float S = g_sum;
    float inv = (S > 0.0f) ? (1.0f / S) : 0.0f;
    float4 v = reinterpret_cast<float4*>(out)[i];
    v.x *= inv; v.y *= inv; v.z *= inv; v.w *= inv;
    v.x = (v.x > 0.0f) ? v.x : expm1f(v.x);
    v.y = (v.y > 0.0f) ? v.y : expm1f(v.y);
    v.z = (v.z > 0.0f) ? v.z : expm1f(v.z);
    v.w = (v.w > 0.0f) ? v.w : expm1f(v.w);
    reinterpret_cast<float4*>(out)[i] = v;
}

// ---------------- launch ----------------
extern "C" void kernel_launch(void* const* d_in, const int* in_sizes, int n_in,
                              void* d_out, int out_size) {
    const float* x   = (const float*)d_in[0];
    const void*  ei  = d_in[1];
    const float* W   = (const float*)d_in[2];
    const float* a   = (const float*)d_in[3];
    float*       out = (float*)d_out;

    int n  = in_sizes[0] / IN_CH;   // 50000
    int nE = in_sizes[1] / 2;       // 800000
    int total = n * OUT_CH;

    detect_kernel<<<1, 32>>>((const unsigned int*)ei);
    init_kernel<<<512, 256>>>(out, total);
    wprep_kernel<<<(32 * 8 * 32 + 255) / 256, 256>>>(W);
    gemm_mma_kernel<<<(n + 127) / 128, 256>>>(x, a, n);
    edge_kernel<<<1184, 256>>>(ei, out, nE);
    elu_kernel<<<(total / 4 + 255) / 256, 256>>>(out, total);
}

// round 10
// speedup vs baseline: 2.1058x; 1.0389x over previous
#include <cuda_runtime.h>
#include <cuda_bf16.h>
#include <math_constants.h>
#include <cstdint>

#define N_NODES_MAX 50000
#define N_EDGES_MAX 800000
#define IN_CH 256
#define OUT_CH 64

// ---------------- scratch (device globals: allocation-free) ----------------
__device__ float g_wh[(size_t)N_NODES_MAX * OUT_CH];   // 12.8 MB
__device__ float g_es[N_NODES_MAX];
__device__ float g_ed[N_NODES_MAX];
__device__ float4 g_wf[32][8][32];                     // B frags [ks][nb][lane]{bh0,bh1,bl0,bl1}
__device__ float g_maxs;
__device__ float g_maxd;
__device__ float g_sum;
__device__ int   g_is64;

// ---------------- helpers ----------------
__device__ __forceinline__ void atomicMaxF(float* addr, float v) {
    if (v >= 0.0f) atomicMax((int*)addr, __float_as_int(v));
    else           atomicMin((unsigned int*)addr, __float_as_uint(v));
}

__device__ __forceinline__ float tf32_round(float v) {
    uint32_t u;
    asm("cvt.rna.tf32.f32 %0, %1;" : "=r"(u) : "f"(v));
    return __uint_as_float(u);
}

__device__ __forceinline__ uint32_t smem_u32(const void* p) {
    uint32_t a;
    asm("{ .reg .u64 t; cvta.to.shared.u64 t, %1; cvt.u32.u64 %0, t; }"
        : "=r"(a) : "l"(p));
    return a;
}

// D += A(16x8,row) * B(8x8,col) in tf32, fp32 accum
__device__ __forceinline__ void mma_tf32(float* c, const uint32_t* a,
                                         uint32_t b0, uint32_t b1) {
    asm volatile(
        "mma.sync.aligned.m16n8k8.row.col.f32.tf32.tf32.f32 "
        "{%0,%1,%2,%3}, {%4,%5,%6,%7}, {%8,%9}, {%0,%1,%2,%3};"
        : "+f"(c[0]), "+f"(c[1]), "+f"(c[2]), "+f"(c[3])
        : "r"(a[0]), "r"(a[1]), "r"(a[2]), "r"(a[3]), "r"(b0), "r"(b1));
}

// ---------------- kernel A: detect edge-index dtype ----------------
__global__ void detect_kernel(const unsigned int* __restrict__ ei_w) {
    if (threadIdx.x == 0) {
        unsigned int any = 0;
        for (int i = 1; i < 256; i += 2) any |= ei_w[i];
        g_is64 = (any == 0) ? 1 : 0;
    }
}

// ---------------- kernel 0: init output + scalars ----------------
__global__ void init_kernel(float* __restrict__ out, int total) {
    int gtid = blockIdx.x * blockDim.x + threadIdx.x;
    if (gtid == 0) {
        g_maxs = -CUDART_INF_F;
        g_maxd = -CUDART_INF_F;
        g_sum = 0.0f;
    }
    float4* o4 = (float4*)out;
    for (int i = gtid; i < total / 4; i += gridDim.x * blockDim.x)
        o4[i] = make_float4(0.f, 0.f, 0.f, 0.f);
}

// ---------------- kernel W: pack W into per-lane tf32 hi/lo B fragments ----
// m16n8k8 col-major B: lane(gid,tig) holds b0=B[k=tig][n=gid], b1=B[k=tig+4][n=gid].
__global__ void wprep_kernel(const float* __restrict__ W) {
    int idx = blockIdx.x * blockDim.x + threadIdx.x;
    if (idx >= 32 * 8 * 32) return;
    int lane = idx & 31, nb = (idx >> 5) & 7, ks = idx >> 8;
    int tig = lane & 3, gid = lane >> 2;
    int k0 = ks * 8 + tig, nn = nb * 8 + gid;
    float w0 = W[(size_t)k0 * OUT_CH + nn];
    float w1 = W[(size_t)(k0 + 4) * OUT_CH + nn];
    float h0 = tf32_round(w0), h1 = tf32_round(w1);
    float l0 = tf32_round(w0 - h0), l1 = tf32_round(w1 - h1);
    g_wf[ks][nb][lane] = make_float4(h0, h1, l0, l1);
}

// ---------------- kernel 1: 3xTF32 mma.sync GEMM, smem-staged A ----------
// 8 warps/CTA, 256 rows/CTA (32 rows/warp = two m16 tiles).
// x staged via cp.async double buffer, 32-col chunks, pad 36 (conflict-free).
#define ROWS_CTA 256
#define XS_STRIDE 36
#define XS_BUF (ROWS_CTA * XS_STRIDE)          // floats per buffer

__global__ __launch_bounds__(256, 2) void gemm_mma_kernel(
    const float* __restrict__ x, const float* __restrict__ a, int n)
{
    extern __shared__ float xs[];              // 2 * XS_BUF floats
    __shared__ float as_[2 * OUT_CH];
    const int tid = threadIdx.x, wid = tid >> 5, lane = tid & 31;
    const int gid = lane >> 2, tig = lane & 3;
    if (tid < 128) as_[tid] = a[tid];

    const int row0 = blockIdx.x * ROWS_CTA;
    const uint32_t sbase = smem_u32(xs);

    // ---- chunk loader: 256 rows x 32 cols, 8 x 16B per thread ----
    auto load_chunk = [&](int c, int buf) {
#pragma unroll
        for (int i = 0; i < 8; i++) {
            int linear = i * 256 + tid;
            int r = linear >> 3, q = linear & 7;
            int gr = row0 + r;
            const float* src =
                x + (size_t)(gr < n ? gr : 0) * IN_CH + c * 32 + q * 4;
            uint32_t dst = sbase + (uint32_t)(buf * XS_BUF + r * XS_STRIDE + q * 4) * 4u;
            int sz = (gr < n) ? 16 : 0;
            asm volatile("cp.async.cg.shared.global [%0], [%1], 16, %2;"
                         :: "r"(dst), "l"(src), "r"(sz));
        }
        asm volatile("cp.async.commit_group;");
    };

    float acc[2][8][4];
#pragma unroll
    for (int t = 0; t < 2; t++)
#pragma unroll
        for (int nb = 0; nb < 8; nb++)
#pragma unroll
            for (int j = 0; j < 4; j++) acc[t][nb][j] = 0.0f;

    load_chunk(0, 0);

    for (int c = 0; c < 8; c++) {
        if (c < 7) {
            load_chunk(c + 1, (c + 1) & 1);
            asm volatile("cp.async.wait_group 1;");
        } else {
            asm volatile("cp.async.wait_group 0;");
        }
        __syncthreads();

        const float* xb = xs + (c & 1) * XS_BUF;
#pragma unroll
        for (int kk = 0; kk < 4; kk++) {
            const int ks = c * 4 + kk;
            const int cb = kk * 8;
            uint32_t ah[2][4], al[2][4];
#pragma unroll
            for (int t = 0; t < 2; t++) {
                int rl = wid * 32 + t * 16 + gid;
                float x0 = xb[rl * XS_STRIDE + cb + tig];
                float x1 = xb[(rl + 8) * XS_STRIDE + cb + tig];
                float x2 = xb[rl * XS_STRIDE + cb + tig + 4];
                float x3 = xb[(rl + 8) * XS_STRIDE + cb + tig + 4];
                float h;
                h = tf32_round(x0); ah[t][0] = __float_as_uint(h); al[t][0] = __float_as_uint(tf32_round(x0 - h));
                h = tf32_round(x1); ah[t][1] = __float_as_uint(h); al[t][1] = __float_as_uint(tf32_round(x1 - h));
                h = tf32_round(x2); ah[t][2] = __float_as_uint(h); al[t][2] = __float_as_uint(tf32_round(x2 - h));
                h = tf32_round(x3); ah[t][3] = __float_as_uint(h); al[t][3] = __float_as_uint(tf32_round(x3 - h));
            }
#pragma unroll
            for (int nb = 0; nb < 8; nb++) {
                float4 f = __ldg(&g_wf[ks][nb][lane]);
                uint32_t bh0 = __float_as_uint(f.x), bh1 = __float_as_uint(f.y);
                uint32_t bl0 = __float_as_uint(f.z), bl1 = __float_as_uint(f.w);
                mma_tf32(acc[0][nb], ah[0], bh0, bh1);
                mma_tf32(acc[0][nb], ah[0], bl0, bl1);
                mma_tf32(acc[0][nb], al[0], bh0, bh1);
                mma_tf32(acc[1][nb], ah[1], bh0, bh1);
                mma_tf32(acc[1][nb], ah[1], bl0, bl1);
                mma_tf32(acc[1][nb], al[1], bh0, bh1);
            }
        }
        __syncthreads();
    }

    // ---- epilogue: wh stores + es/ed dots + maxes ----
    float ms = -CUDART_INF_F, md = -CUDART_INF_F;
#pragma unroll
    for (int t = 0; t < 2; t++) {
        const int r0 = row0 + wid * 32 + t * 16 + gid;
        const int r8 = r0 + 8;
        const bool v0 = r0 < n, v8 = r8 < n;
        float es0 = 0.f, ed0 = 0.f, es8 = 0.f, ed8 = 0.f;
#pragma unroll
        for (int nb = 0; nb < 8; nb++) {
            int c0 = nb * 8 + 2 * tig;
            es0 += acc[t][nb][0] * as_[c0] + acc[t][nb][1] * as_[c0 + 1];
            ed0 += acc[t][nb][0] * as_[OUT_CH + c0] + acc[t][nb][1] * as_[OUT_CH + c0 + 1];
            es8 += acc[t][nb][2] * as_[c0] + acc[t][nb][3] * as_[c0 + 1];
            ed8 += acc[t][nb][2] * as_[OUT_CH + c0] + acc[t][nb][3] * as_[OUT_CH + c0 + 1];
            if (v0) *(float2*)&g_wh[(size_t)r0 * OUT_CH + c0] =
                make_float2(acc[t][nb][0], acc[t][nb][1]);
            if (v8) *(float2*)&g_wh[(size_t)r8 * OUT_CH + c0] =
                make_float2(acc[t][nb][2], acc[t][nb][3]);
        }
#pragma unroll
        for (int o = 1; o <= 2; o <<= 1) {
            es0 += __shfl_xor_sync(0xFFFFFFFFu, es0, o);
            ed0 += __shfl_xor_sync(0xFFFFFFFFu, ed0, o);
            es8 += __shfl_xor_sync(0xFFFFFFFFu, es8, o);
            ed8 += __shfl_xor_sync(0xFFFFFFFFu, ed8, o);
        }
        if (tig == 0 && v0) { g_es[r0] = es0; g_ed[r0] = ed0; }
        if (tig == 0 && v8) { g_es[r8] = es8; g_ed[r8] = ed8; }
        ms = fmaxf(ms, fmaxf(v0 ? es0 : -CUDART_INF_F, v8 ? es8 : -CUDART_INF_F));
        md = fmaxf(md, fmaxf(v0 ? ed0 : -CUDART_INF_F, v8 ? ed8 : -CUDART_INF_F));
    }
#pragma unroll
    for (int o = 16; o > 0; o >>= 1) {
        ms = fmaxf(ms, __shfl_xor_sync(0xFFFFFFFFu, ms, o));
        md = fmaxf(md, __shfl_xor_sync(0xFFFFFFFFu, md, o));
    }
    if (lane == 0) {
        atomicMaxF(&g_maxs, ms);
        atomicMaxF(&g_maxd, md);
    }
}

// ---------------- kernel 2: FUSED edge pass (unchanged) ----------------
// Masked edges have weight exp(NEG_BIG-M) == +0.0 exactly, so skipping them
// is bit-identical. M = max(es)+max(ed) >= true max: valid softmax shift.
__global__ void edge_kernel(const void* __restrict__ ei_raw,
                            float* __restrict__ out, int nE) {
    const int lane   = threadIdx.x & 31;
    const int warpId = (blockIdx.x * blockDim.x + threadIdx.x) >> 5;
    const int nWarps = (gridDim.x * blockDim.x) >> 5;
    const int is64   = g_is64;
    const float M    = g_maxs + g_maxd;
    const int half   = lane >> 4;
    const int t      = lane & 15;

    float sumacc = 0.0f;

    for (int base = warpId * 32; base < nE; base += nWarps * 32) {
        int e = base + lane;
        int src = 0, dst = 0;
        float v = -1.0f;
        if (e < nE) {
            if (is64) {
                src = (int)((const long long*)ei_raw)[e];
                dst = (int)((const long long*)ei_raw)[nE + e];
            } else {
                src = ((const int*)ei_raw)[e];
                dst = ((const int*)ei_raw)[nE + e];
            }
            v = g_es[src] + g_ed[dst];
        }
        bool keep = v > 0.0f;
        unsigned mask = __ballot_sync(0xFFFFFFFFu, keep);
        float w = keep ? expf(v - M) : 0.0f;
        sumacc += w;

        while (mask) {
            int l0 = __ffs(mask) - 1; mask &= mask - 1;
            int l1 = -1;
            if (mask) { l1 = __ffs(mask) - 1; mask &= mask - 1; }
            int sl = half ? l1 : l0;
            float ws = __shfl_sync(0xFFFFFFFFu, w,   sl < 0 ? 0 : sl);
            int   ss = __shfl_sync(0xFFFFFFFFu, src, sl < 0 ? 0 : sl);
            int   ds = __shfl_sync(0xFFFFFFFFu, dst, sl < 0 ? 0 : sl);
            if (sl >= 0) {
                float4 vv = *reinterpret_cast<const float4*>(
                    &g_wh[(size_t)ss * OUT_CH + t * 4]);
                float* o = &out[(size_t)ds * OUT_CH + t * 4];
                asm volatile("red.global.add.v4.f32 [%0], {%1, %2, %3, %4};"
                             :: "l"(o), "f"(ws * vv.x), "f"(ws * vv.y),
                                "f"(ws * vv.z), "f"(ws * vv.w)
                             : "memory");
            }
        }
    }

#pragma unroll
    for (int o = 16; o > 0; o >>= 1)
        sumacc += __shfl_xor_sync(0xFFFFFFFFu, sumacc, o);
    if (lane == 0 && sumacc > 0.0f) atomicAdd(&g_sum, sumacc);
}

// ---------------- kernel 3: normalize + ELU in place ----------------
__global__ void elu_kernel(float* __restrict__ out, int total) {
    int i = blockIdx.x * blockDim.x + threadIdx.x;
    if (i >= total / 4) return;
    float S = g_sum;
    float inv = (S > 0.0f) ? (1.0f / S) : 0.0f;
    float4 v = reinterpret_cast<float4*>(out)[i];
    v.x *= inv; v.y *= inv; v.z *= inv; v.w *= inv;
    v.x = (v.x > 0.0f) ? v.x : expm1f(v.x);
    v.y = (v.y > 0.0f) ? v.y : expm1f(v.y);
    v.z = (v.z > 0.0f) ? v.z : expm1f(v.z);
    v.w = (v.w > 0.0f) ? v.w : expm1f(v.w);
    reinterpret_cast<float4*>(out)[i] = v;
}

// ---------------- launch ----------------
extern "C" void kernel_launch(void* const* d_in, const int* in_sizes, int n_in,
                              void* d_out, int out_size) {
    const float* x   = (const float*)d_in[0];
    const void*  ei  = d_in[1];
    const float* W   = (const float*)d_in[2];
    const float* a   = (const float*)d_in[3];
    float*       out = (float*)d_out;

    int n  = in_sizes[0] / IN_CH;   // 50000
    int nE = in_sizes[1] / 2;       // 800000
    int total = n * OUT_CH;

    const int smem_bytes = 2 * XS_BUF * sizeof(float);   // 73728
    cudaFuncSetAttribute(gemm_mma_kernel,
                         cudaFuncAttributeMaxDynamicSharedMemorySize, smem_bytes);

    detect_kernel<<<1, 32>>>((const unsigned int*)ei);
    init_kernel<<<512, 256>>>(out, total);
    wprep_kernel<<<(32 * 8 * 32 + 255) / 256, 256>>>(W);
    gemm_mma_kernel<<<(n + ROWS_CTA - 1) / ROWS_CTA, 256, smem_bytes>>>(x, a, n);
    edge_kernel<<<1184, 256>>>(ei, out, nE);
    elu_kernel<<<(total / 4 + 255) / 256, 256>>>(out, total);
}

// round 11
// speedup vs baseline: 2.4785x; 1.1770x over previous
#include <cuda_runtime.h>
#include <cuda_bf16.h>
#include <math_constants.h>
#include <cstdint>

#define N_NODES_MAX 50000
#define N_EDGES_MAX 800000
#define IN_CH 256
#define OUT_CH 64

// ---------------- scratch (device globals: allocation-free) ----------------
__device__ float g_wh[(size_t)N_NODES_MAX * OUT_CH];   // 12.8 MB
__device__ float g_es[N_NODES_MAX];
__device__ float g_ed[N_NODES_MAX];
__device__ uint4 g_wfb[16][8][32];   // B frags [ks][nb][lane] = {bh0,bh1,bl0,bl1} bf16x2
__device__ float g_maxs;
__device__ float g_maxd;
__device__ float g_sum;
__device__ int   g_is64;

// ---------------- helpers ----------------
__device__ __forceinline__ void atomicMaxF(float* addr, float v) {
    if (v >= 0.0f) atomicMax((int*)addr, __float_as_int(v));
    else           atomicMin((unsigned int*)addr, __float_as_uint(v));
}

__device__ __forceinline__ uint32_t smem_u32(const void* p) {
    uint32_t a;
    asm("{ .reg .u64 t; cvta.to.shared.u64 t, %1; cvt.u32.u64 %0, t; }"
        : "=r"(a) : "l"(p));
    return a;
}

// pack two floats to bf16x2 (f0 -> low half, f1 -> high half)
__device__ __forceinline__ uint32_t bf16x2_pack(float f0, float f1) {
    uint32_t r;
    asm("cvt.rn.bf16x2.f32 %0, %1, %2;" : "=r"(r) : "f"(f1), "f"(f0));
    return r;
}

// hi/lo split of a float pair into bf16x2 regs
__device__ __forceinline__ void bf16_split(float f0, float f1,
                                           uint32_t& h, uint32_t& l) {
    h = bf16x2_pack(f0, f1);
    float g0 = __uint_as_float(h << 16);
    float g1 = __uint_as_float(h & 0xFFFF0000u);
    l = bf16x2_pack(f0 - g0, f1 - g1);
}

// D(16x8) += A(16x16 bf16) * B(16x8 bf16), fp32 accum
__device__ __forceinline__ void mma_bf16(float* c, const uint32_t* a,
                                         uint32_t b0, uint32_t b1) {
    asm volatile(
        "mma.sync.aligned.m16n8k16.row.col.f32.bf16.bf16.f32 "
        "{%0,%1,%2,%3}, {%4,%5,%6,%7}, {%8,%9}, {%0,%1,%2,%3};"
        : "+f"(c[0]), "+f"(c[1]), "+f"(c[2]), "+f"(c[3])
        : "r"(a[0]), "r"(a[1]), "r"(a[2]), "r"(a[3]), "r"(b0), "r"(b1));
}

#define LDMATRIX_X4(r, addr)                                          \
    asm volatile("ldmatrix.sync.aligned.m8n8.x4.shared.b16 "          \
                 "{%0,%1,%2,%3}, [%4];"                               \
                 : "=r"((r)[0]), "=r"((r)[1]), "=r"((r)[2]), "=r"((r)[3]) \
                 : "r"(addr))

// ---------------- kernel A: detect edge-index dtype ----------------
__global__ void detect_kernel(const unsigned int* __restrict__ ei_w) {
    if (threadIdx.x == 0) {
        unsigned int any = 0;
        for (int i = 1; i < 256; i += 2) any |= ei_w[i];
        g_is64 = (any == 0) ? 1 : 0;
    }
}

// ---------------- kernel 0: init output + scalars ----------------
__global__ void init_kernel(float* __restrict__ out, int total) {
    int gtid = blockIdx.x * blockDim.x + threadIdx.x;
    if (gtid == 0) {
        g_maxs = -CUDART_INF_F;
        g_maxd = -CUDART_INF_F;
        g_sum = 0.0f;
    }
    float4* o4 = (float4*)out;
    for (int i = gtid; i < total / 4; i += gridDim.x * blockDim.x)
        o4[i] = make_float4(0.f, 0.f, 0.f, 0.f);
}

// ---------------- kernel W: pack W into per-lane bf16 hi/lo B fragments ----
// m16n8k16 col-major B frag: b0 = {B[k0+2tig], B[k0+2tig+1]}[n],
// b1 = same at k+8. hi/lo split per element.
__global__ void wprep_kernel(const float* __restrict__ W) {
    int idx = blockIdx.x * blockDim.x + threadIdx.x;
    if (idx >= 16 * 8 * 32) return;
    int lane = idx & 31, nb = (idx >> 5) & 7, ks = idx >> 8;
    int tig = lane & 3, gid = lane >> 2;
    int nn = nb * 8 + gid;
    int k0 = ks * 16 + 2 * tig;
    float w00 = W[(size_t)k0 * OUT_CH + nn];
    float w01 = W[(size_t)(k0 + 1) * OUT_CH + nn];
    float w10 = W[(size_t)(k0 + 8) * OUT_CH + nn];
    float w11 = W[(size_t)(k0 + 9) * OUT_CH + nn];
    uint4 f;
    bf16_split(w00, w01, f.x, f.z);
    bf16_split(w10, w11, f.y, f.w);
    g_wfb[ks][nb][lane] = f;
}

// ---------------- kernel 1: 3x bf16 mma.sync GEMM + attention epilogue ----
// 8 warps/CTA, 128 rows/CTA, 16 rows/warp. x streamed: LDG fp32 (register
// staged) -> bf16 hi/lo split -> smem (pad-80B rows, ldmatrix conflict-free),
// double buffered, one bar.sync per 32-col chunk.
#define ROWS_CTA 128
#define RSTRIDE 80                         // bytes per smem row (64B data + 16 pad)
#define HBUF (ROWS_CTA * RSTRIDE)          // one hi or lo buffer (10240 B)

__global__ __launch_bounds__(256, 2) void gemm_mma_kernel(
    const float* __restrict__ x, const float* __restrict__ a, int n)
{
    __shared__ __align__(16) char sbuf[2 * 2 * HBUF];  // [dbuf][hi/lo] 40 KB
    __shared__ float as_[2 * OUT_CH];
    const int tid = threadIdx.x, wid = tid >> 5, lane = tid & 31;
    const int gid = lane >> 2, tig = lane & 3;
    if (tid < 128) as_[tid] = a[tid];

    const int row0 = blockIdx.x * ROWS_CTA;
    const uint32_t sb = smem_u32(sbuf);

    // staging geometry: thread owns row r = tid>>1, 16 cols at (tid&1)*16
    const int sr = tid >> 1, sh = tid & 1;
    const int gr = row0 + sr;
    const float* xsrc = x + (size_t)(gr < n ? gr : 0) * IN_CH + sh * 16;
    const uint32_t sts_off = (uint32_t)(sr * RSTRIDE + sh * 32);

    // ldmatrix base addresses (per hi/lo, per dbuf): row = wid*16+(lane&15),
    // col halves at (lane>>4)*16
    const uint32_t lm_off =
        (uint32_t)((wid * 16 + (lane & 15)) * RSTRIDE + (lane >> 4) * 16);

    float4 st[4];
    auto ldg_chunk = [&](int c) {
#pragma unroll
        for (int i = 0; i < 4; i++)
            st[i] = __ldg((const float4*)(xsrc + c * 32) + i);
    };
    auto sts_chunk = [&](int buf) {
        uint32_t hi[8], lo[8];
#pragma unroll
        for (int i = 0; i < 4; i++) {
            bf16_split(st[i].x, st[i].y, hi[2 * i], lo[2 * i]);
            bf16_split(st[i].z, st[i].w, hi[2 * i + 1], lo[2 * i + 1]);
        }
        uint32_t dh = sb + (uint32_t)(buf * 2 * HBUF) + sts_off;
        uint32_t dl = dh + HBUF;
        asm volatile("st.shared.v4.b32 [%0], {%1,%2,%3,%4};"
                     :: "r"(dh), "r"(hi[0]), "r"(hi[1]), "r"(hi[2]), "r"(hi[3]));
        asm volatile("st.shared.v4.b32 [%0], {%1,%2,%3,%4};"
                     :: "r"(dh + 16), "r"(hi[4]), "r"(hi[5]), "r"(hi[6]), "r"(hi[7]));
        asm volatile("st.shared.v4.b32 [%0], {%1,%2,%3,%4};"
                     :: "r"(dl), "r"(lo[0]), "r"(lo[1]), "r"(lo[2]), "r"(lo[3]));
        asm volatile("st.shared.v4.b32 [%0], {%1,%2,%3,%4};"
                     :: "r"(dl + 16), "r"(lo[4]), "r"(lo[5]), "r"(lo[6]), "r"(lo[7]));
    };

    float acc[8][4];
#pragma unroll
    for (int nb = 0; nb < 8; nb++)
#pragma unroll
        for (int j = 0; j < 4; j++) acc[nb][j] = 0.0f;

    // prologue: chunk 0
    ldg_chunk(0);
    sts_chunk(0);
    __syncthreads();

    for (int c = 0; c < 8; c++) {
        if (c < 7) ldg_chunk(c + 1);        // overlap with MMA below

        const uint32_t abase = sb + (uint32_t)((c & 1) * 2 * HBUF) + lm_off;
#pragma unroll
        for (int ks2 = 0; ks2 < 2; ks2++) {
            uint32_t ah[4], al[4];
            LDMATRIX_X4(ah, abase + ks2 * 32);
            LDMATRIX_X4(al, abase + HBUF + ks2 * 32);
            const int ks = c * 2 + ks2;
            const uint4* bp = &g_wfb[ks][0][lane];
#pragma unroll
            for (int nb = 0; nb < 8; nb++) {
                uint4 b = __ldg(bp + nb * 32);
                mma_bf16(acc[nb], ah, b.x, b.y);   // hi*hi
                mma_bf16(acc[nb], ah, b.z, b.w);   // hi*lo
                mma_bf16(acc[nb], al, b.x, b.y);   // lo*hi
            }
        }

        if (c < 7) {
            sts_chunk((c + 1) & 1);   // buf last read at chunk c-1, sync'd below
            __syncthreads();
        }
    }

    // ---- epilogue: wh stores + es/ed dots + maxes ----
    const int r0 = row0 + wid * 16 + gid;
    const int r8 = r0 + 8;
    const bool v0 = r0 < n, v8 = r8 < n;
    float es0 = 0.f, ed0 = 0.f, es8 = 0.f, ed8 = 0.f;
#pragma unroll
    for (int nb = 0; nb < 8; nb++) {
        int c0 = nb * 8 + 2 * tig;
        es0 += acc[nb][0] * as_[c0] + acc[nb][1] * as_[c0 + 1];
        ed0 += acc[nb][0] * as_[OUT_CH + c0] + acc[nb][1] * as_[OUT_CH + c0 + 1];
        es8 += acc[nb][2] * as_[c0] + acc[nb][3] * as_[c0 + 1];
        ed8 += acc[nb][2] * as_[OUT_CH + c0] + acc[nb][3] * as_[OUT_CH + c0 + 1];
        if (v0) *(float2*)&g_wh[(size_t)r0 * OUT_CH + c0] =
            make_float2(acc[nb][0], acc[nb][1]);
        if (v8) *(float2*)&g_wh[(size_t)r8 * OUT_CH + c0] =
            make_float2(acc[nb][2], acc[nb][3]);
    }
#pragma unroll
    for (int o = 1; o <= 2; o <<= 1) {
        es0 += __shfl_xor_sync(0xFFFFFFFFu, es0, o);
        ed0 += __shfl_xor_sync(0xFFFFFFFFu, ed0, o);
        es8 += __shfl_xor_sync(0xFFFFFFFFu, es8, o);
        ed8 += __shfl_xor_sync(0xFFFFFFFFu, ed8, o);
    }
    if (tig == 0 && v0) { g_es[r0] = es0; g_ed[r0] = ed0; }
    if (tig == 0 && v8) { g_es[r8] = es8; g_ed[r8] = ed8; }

    float ms = fmaxf(v0 ? es0 : -CUDART_INF_F, v8 ? es8 : -CUDART_INF_F);
    float md = fmaxf(v0 ? ed0 : -CUDART_INF_F, v8 ? ed8 : -CUDART_INF_F);
#pragma unroll
    for (int o = 16; o > 0; o >>= 1) {
        ms = fmaxf(ms, __shfl_xor_sync(0xFFFFFFFFu, ms, o));
        md = fmaxf(md, __shfl_xor_sync(0xFFFFFFFFu, md, o));
    }
    if (lane == 0) {
        atomicMaxF(&g_maxs, ms);
        atomicMaxF(&g_maxd, md);
    }
}

// ---------------- kernel 2: FUSED edge pass (unchanged) ----------------
// Masked edges have weight exp(NEG_BIG-M) == +0.0 exactly, so skipping them
// is bit-identical. M = max(es)+max(ed) >= true max: valid softmax shift.
__global__ void edge_kernel(const void* __restrict__ ei_raw,
                            float* __restrict__ out, int nE) {
    const int lane   = threadIdx.x & 31;
    const int warpId = (blockIdx.x * blockDim.x + threadIdx.x) >> 5;
    const int nWarps = (gridDim.x * blockDim.x) >> 5;
    const int is64   = g_is64;
    const float M    = g_maxs + g_maxd;
    const int half   = lane >> 4;
    const int t      = lane & 15;

    float sumacc = 0.0f;

    for (int base = warpId * 32; base < nE; base += nWarps * 32) {
        int e = base + lane;
        int src = 0, dst = 0;
        float v = -1.0f;
        if (e < nE) {
            if (is64) {
                src = (int)((const long long*)ei_raw)[e];
                dst = (int)((const long long*)ei_raw)[nE + e];
            } else {
                src = ((const int*)ei_raw)[e];
                dst = ((const int*)ei_raw)[nE + e];
            }
            v = g_es[src] + g_ed[dst];
        }
        bool keep = v > 0.0f;
        unsigned mask = __ballot_sync(0xFFFFFFFFu, keep);
        float w = keep ? expf(v - M) : 0.0f;
        sumacc += w;

        while (mask) {
            int l0 = __ffs(mask) - 1; mask &= mask - 1;
            int l1 = -1;
            if (mask) { l1 = __ffs(mask) - 1; mask &= mask - 1; }
            int sl = half ? l1 : l0;
            float ws = __shfl_sync(0xFFFFFFFFu, w,   sl < 0 ? 0 : sl);
            int   ss = __shfl_sync(0xFFFFFFFFu, src, sl < 0 ? 0 : sl);
            int   ds = __shfl_sync(0xFFFFFFFFu, dst, sl < 0 ? 0 : sl);
            if (sl >= 0) {
                float4 vv = *reinterpret_cast<const float4*>(
                    &g_wh[(size_t)ss * OUT_CH + t * 4]);
                float* o = &out[(size_t)ds * OUT_CH + t * 4];
                asm volatile("red.global.add.v4.f32 [%0], {%1, %2, %3, %4};"
                             :: "l"(o), "f"(ws * vv.x), "f"(ws * vv.y),
                                "f"(ws * vv.z), "f"(ws * vv.w)
                             : "memory");
            }
        }
    }

#pragma unroll
    for (int o = 16; o > 0; o >>= 1)
        sumacc += __shfl_xor_sync(0xFFFFFFFFu, sumacc, o);
    if (lane == 0 && sumacc > 0.0f) atomicAdd(&g_sum, sumacc);
}

// ---------------- kernel 3: normalize + ELU in place ----------------
__global__ void elu_kernel(float* __restrict__ out, int total) {
    int i = blockIdx.x * blockDim.x + threadIdx.x;
    if (i >= total / 4) return;
    float S = g_sum;
    float inv = (S > 0.0f) ? (1.0f / S) : 0.0f;
    float4 v = reinterpret_cast<float4*>(out)[i];
    v.x *= inv; v.y *= inv; v.z *= inv; v.w *= inv;
    v.x = (v.x > 0.0f) ? v.x : expm1f(v.x);
    v.y = (v.y > 0.0f) ? v.y : expm1f(v.y);
    v.z = (v.z > 0.0f) ? v.z : expm1f(v.z);
    v.w = (v.w > 0.0f) ? v.w : expm1f(v.w);
    reinterpret_cast<float4*>(out)[i] = v;
}

// ---------------- launch ----------------
extern "C" void kernel_launch(void* const* d_in, const int* in_sizes, int n_in,
                              void* d_out, int out_size) {
    const float* x   = (const float*)d_in[0];
    const void*  ei  = d_in[1];
    const float* W   = (const float*)d_in[2];
    const float* a   = (const float*)d_in[3];
    float*       out = (float*)d_out;

    int n  = in_sizes[0] / IN_CH;   // 50000
    int nE = in_sizes[1] / 2;       // 800000
    int total = n * OUT_CH;

    detect_kernel<<<1, 32>>>((const unsigned int*)ei);
    init_kernel<<<512, 256>>>(out, total);
    wprep_kernel<<<16, 256>>>(W);
    gemm_mma_kernel<<<(n + ROWS_CTA - 1) / ROWS_CTA, 256>>>(x, a, n);
    edge_kernel<<<1184, 256>>>(ei, out, nE);
    elu_kernel<<<(total / 4 + 255) / 256, 256>>>(out, total);
}

// round 14
// speedup vs baseline: 2.4934x; 1.0060x over previous
#include <cuda_runtime.h>
#include <cuda_bf16.h>
#include <math_constants.h>
#include <cstdint>

#define N_NODES_MAX 50000
#define N_EDGES_MAX 800000
#define IN_CH 256
#define OUT_CH 64

// ---------------- scratch (device globals: allocation-free) ----------------
__device__ float g_wh[(size_t)N_NODES_MAX * OUT_CH];   // 12.8 MB
__device__ float g_es[N_NODES_MAX];
__device__ float g_ed[N_NODES_MAX];
__device__ uint4 g_wfb[16][8][32];   // B frags [ks][nb][lane] = {bh0,bh1,bl0,bl1} bf16x2
__device__ float g_maxs;
__device__ float g_maxd;
__device__ float g_sum;
__device__ int   g_is64;

// ---------------- helpers ----------------
__device__ __forceinline__ void atomicMaxF(float* addr, float v) {
    if (v >= 0.0f) atomicMax((int*)addr, __float_as_int(v));
    else           atomicMin((unsigned int*)addr, __float_as_uint(v));
}

__device__ __forceinline__ uint32_t smem_u32(const void* p) {
    uint32_t a;
    asm("{ .reg .u64 t; cvta.to.shared.u64 t, %1; cvt.u32.u64 %0, t; }"
        : "=r"(a) : "l"(p));
    return a;
}

// pack two floats to bf16x2 (f0 -> low half, f1 -> high half)
__device__ __forceinline__ uint32_t bf16x2_pack(float f0, float f1) {
    uint32_t r;
    asm("cvt.rn.bf16x2.f32 %0, %1, %2;" : "=r"(r) : "f"(f1), "f"(f0));
    return r;
}

// hi/lo split of a float pair into bf16x2 regs
__device__ __forceinline__ void bf16_split(float f0, float f1,
                                           uint32_t& h, uint32_t& l) {
    h = bf16x2_pack(f0, f1);
    float g0 = __uint_as_float(h << 16);
    float g1 = __uint_as_float(h & 0xFFFF0000u);
    l = bf16x2_pack(f0 - g0, f1 - g1);
}

// D(16x8) += A(16x16 bf16) * B(16x8 bf16), fp32 accum
__device__ __forceinline__ void mma_bf16(float* c, const uint32_t* a,
                                         uint32_t b0, uint32_t b1) {
    asm volatile(
        "mma.sync.aligned.m16n8k16.row.col.f32.bf16.bf16.f32 "
        "{%0,%1,%2,%3}, {%4,%5,%6,%7}, {%8,%9}, {%0,%1,%2,%3};"
        : "+f"(c[0]), "+f"(c[1]), "+f"(c[2]), "+f"(c[3])
        : "r"(a[0]), "r"(a[1]), "r"(a[2]), "r"(a[3]), "r"(b0), "r"(b1));
}

#define LDMATRIX_X4(r, addr)                                          \
    asm volatile("ldmatrix.sync.aligned.m8n8.x4.shared.b16 "          \
                 "{%0,%1,%2,%3}, [%4];"                               \
                 : "=r"((r)[0]), "=r"((r)[1]), "=r"((r)[2]), "=r"((r)[3]) \
                 : "r"(addr))

// ---------------- kernel A: detect edge-index dtype ----------------
__global__ void detect_kernel(const unsigned int* __restrict__ ei_w) {
    if (threadIdx.x == 0) {
        unsigned int any = 0;
        for (int i = 1; i < 256; i += 2) any |= ei_w[i];
        g_is64 = (any == 0) ? 1 : 0;
    }
}

// ---------------- kernel 0: init output + scalars ----------------
__global__ void init_kernel(float* __restrict__ out, int total) {
    int gtid = blockIdx.x * blockDim.x + threadIdx.x;
    if (gtid == 0) {
        g_maxs = -CUDART_INF_F;
        g_maxd = -CUDART_INF_F;
        g_sum = 0.0f;
    }
    float4* o4 = (float4*)out;
    for (int i = gtid; i < total / 4; i += gridDim.x * blockDim.x)
        o4[i] = make_float4(0.f, 0.f, 0.f, 0.f);
}

// ---------------- kernel W: pack W into per-lane bf16 hi/lo B fragments ----
// m16n8k16 col-major B frag: b0 = {B[k0+2tig], B[k0+2tig+1]}[n],
// b1 = same at k+8. hi/lo split per element.
__global__ void wprep_kernel(const float* __restrict__ W) {
    int idx = blockIdx.x * blockDim.x + threadIdx.x;
    if (idx >= 16 * 8 * 32) return;
    int lane = idx & 31, nb = (idx >> 5) & 7, ks = idx >> 8;
    int tig = lane & 3, gid = lane >> 2;
    int nn = nb * 8 + gid;
    int k0 = ks * 16 + 2 * tig;
    float w00 = W[(size_t)k0 * OUT_CH + nn];
    float w01 = W[(size_t)(k0 + 1) * OUT_CH + nn];
    float w10 = W[(size_t)(k0 + 8) * OUT_CH + nn];
    float w11 = W[(size_t)(k0 + 9) * OUT_CH + nn];
    uint4 f;
    bf16_split(w00, w01, f.x, f.z);
    bf16_split(w10, w11, f.y, f.w);
    g_wfb[ks][nb][lane] = f;
}

// ---------------- kernel 1: 3x bf16 mma.sync GEMM, occupancy-first ----
// 8 warps/CTA, 128 rows/CTA, 16 rows/warp; 16 chunks of k=16.
// Per chunk/thread: 2x LDG.128 (8 floats of one row-half) -> bf16 hi/lo
// -> 2x STS.128. Stride 48B rows: ldmatrix phases hit all 32 banks once.
// 3 CTAs/SM (85-reg cap) for latency hiding; one bar.sync per chunk.
#define ROWS_CTA 128
#define RSTRIDE 48                         // 32B data + 16B pad
#define HBUF (ROWS_CTA * RSTRIDE)          // 6144 B per hi|lo buffer

__global__ __launch_bounds__(256, 3) void gemm_mma_kernel(
    const float* __restrict__ x, const float* __restrict__ a, int n)
{
    __shared__ __align__(16) char sbuf[2 * 2 * HBUF];  // [dbuf][hi|lo] 24 KB
    __shared__ float as_[2 * OUT_CH];
    const int tid = threadIdx.x, wid = tid >> 5, lane = tid & 31;
    const int gid = lane >> 2, tig = lane & 3;
    if (tid < 128) as_[tid] = a[tid];

    const int row0 = blockIdx.x * ROWS_CTA;
    const uint32_t sb = smem_u32(sbuf);

    // staging geometry: thread owns row sr = tid>>1, 8 cols at (tid&1)*8
    const int sr = tid >> 1, sh = tid & 1;
    const int gr = row0 + sr;
    const float* xsrc = x + (size_t)(gr < n ? gr : 0) * IN_CH + sh * 8;
    const uint32_t sts_off = (uint32_t)(sr * RSTRIDE + sh * 16);

    // ldmatrix: rows wid*16+(lane&15), col half (lane>>4)*16B
    const uint32_t lm_off =
        (uint32_t)((wid * 16 + (lane & 15)) * RSTRIDE + (lane >> 4) * 16);

    float4 st[2];
    auto ldg_chunk = [&](int c) {
        st[0] = __ldg((const float4*)(xsrc + c * 16));
        st[1] = __ldg((const float4*)(xsrc + c * 16 + 4));
    };
    auto sts_chunk = [&](int buf) {
        uint32_t hi[4], lo[4];
        bf16_split(st[0].x, st[0].y, hi[0], lo[0]);
        bf16_split(st[0].z, st[0].w, hi[1], lo[1]);
        bf16_split(st[1].x, st[1].y, hi[2], lo[2]);
        bf16_split(st[1].z, st[1].w, hi[3], lo[3]);
        uint32_t dh = sb + (uint32_t)(buf * 2 * HBUF) + sts_off;
        asm volatile("st.shared.v4.b32 [%0], {%1,%2,%3,%4};"
                     :: "r"(dh), "r"(hi[0]), "r"(hi[1]), "r"(hi[2]), "r"(hi[3]));
        asm volatile("st.shared.v4.b32 [%0], {%1,%2,%3,%4};"
                     :: "r"(dh + HBUF), "r"(lo[0]), "r"(lo[1]), "r"(lo[2]), "r"(lo[3]));
    };

    float acc[8][4];
#pragma unroll
    for (int nb = 0; nb < 8; nb++)
#pragma unroll
        for (int j = 0; j < 4; j++) acc[nb][j] = 0.0f;

    // prologue
    ldg_chunk(0);
    sts_chunk(0);
    __syncthreads();

#pragma unroll 4
    for (int c = 0; c < 16; c++) {
        if (c < 15) ldg_chunk(c + 1);       // in flight under the MMAs

        const uint32_t abase = sb + (uint32_t)((c & 1) * 2 * HBUF) + lm_off;
        uint32_t ah[4], al[4];
        LDMATRIX_X4(ah, abase);
        LDMATRIX_X4(al, abase + HBUF);
        const uint4* bp = &g_wfb[c][0][lane];
#pragma unroll
        for (int nb = 0; nb < 8; nb++) {
            uint4 b = __ldg(bp + nb * 32);
            mma_bf16(acc[nb], ah, b.x, b.y);   // hi*hi
            mma_bf16(acc[nb], ah, b.z, b.w);   // hi*lo
            mma_bf16(acc[nb], al, b.x, b.y);   // lo*hi
        }

        if (c < 15) sts_chunk((c + 1) & 1); // buf free: consumed at c-1, synced
        __syncthreads();
    }

    // ---- epilogue: wh stores + es/ed dots + maxes ----
    const int r0 = row0 + wid * 16 + gid;
    const int r8 = r0 + 8;
    const bool v0 = r0 < n, v8 = r8 < n;
    float es0 = 0.f, ed0 = 0.f, es8 = 0.f, ed8 = 0.f;
#pragma unroll
    for (int nb = 0; nb < 8; nb++) {
        int c0 = nb * 8 + 2 * tig;
        es0 += acc[nb][0] * as_[c0] + acc[nb][1] * as_[c0 + 1];
        ed0 += acc[nb][0] * as_[OUT_CH + c0] + acc[nb][1] * as_[OUT_CH + c0 + 1];
        es8 += acc[nb][2] * as_[c0] + acc[nb][3] * as_[c0 + 1];
        ed8 += acc[nb][2] * as_[OUT_CH + c0] + acc[nb][3] * as_[OUT_CH + c0 + 1];
        if (v0) *(float2*)&g_wh[(size_t)r0 * OUT_CH + c0] =
            make_float2(acc[nb][0], acc[nb][1]);
        if (v8) *(float2*)&g_wh[(size_t)r8 * OUT_CH + c0] =
            make_float2(acc[nb][2], acc[nb][3]);
    }
#pragma unroll
    for (int o = 1; o <= 2; o <<= 1) {
        es0 += __shfl_xor_sync(0xFFFFFFFFu, es0, o);
        ed0 += __shfl_xor_sync(0xFFFFFFFFu, ed0, o);
        es8 += __shfl_xor_sync(0xFFFFFFFFu, es8, o);
        ed8 += __shfl_xor_sync(0xFFFFFFFFu, ed8, o);
    }
    if (tig == 0 && v0) { g_es[r0] = es0; g_ed[r0] = ed0; }
    if (tig == 0 && v8) { g_es[r8] = es8; g_ed[r8] = ed8; }

    float ms = fmaxf(v0 ? es0 : -CUDART_INF_F, v8 ? es8 : -CUDART_INF_F);
    float md = fmaxf(v0 ? ed0 : -CUDART_INF_F, v8 ? ed8 : -CUDART_INF_F);
#pragma unroll
    for (int o = 16; o > 0; o >>= 1) {
        ms = fmaxf(ms, __shfl_xor_sync(0xFFFFFFFFu, ms, o));
        md = fmaxf(md, __shfl_xor_sync(0xFFFFFFFFu, md, o));
    }
    if (lane == 0) {
        atomicMaxF(&g_maxs, ms);
        atomicMaxF(&g_maxd, md);
    }
}

// ---------------- kernel 2: FUSED edge pass (unchanged) ----------------
// Masked edges have weight exp(NEG_BIG-M) == +0.0 exactly, so skipping them
// is bit-identical. M = max(es)+max(ed) >= true max: valid softmax shift.
__global__ void edge_kernel(const void* __restrict__ ei_raw,
                            float* __restrict__ out, int nE) {
    const int lane   = threadIdx.x & 31;
    const int warpId = (blockIdx.x * blockDim.x + threadIdx.x) >> 5;
    const int nWarps = (gridDim.x * blockDim.x) >> 5;
    const int is64   = g_is64;
    const float M    = g_maxs + g_maxd;
    const int half   = lane >> 4;
    const int t      = lane & 15;

    float sumacc = 0.0f;

    for (int base = warpId * 32; base < nE; base += nWarps * 32) {
        int e = base + lane;
        int src = 0, dst = 0;
        float v = -1.0f;
        if (e < nE) {
            if (is64) {
                src = (int)((const long long*)ei_raw)[e];
                dst = (int)((const long long*)ei_raw)[nE + e];
            } else {
                src = ((const int*)ei_raw)[e];
                dst = ((const int*)ei_raw)[nE + e];
            }
            v = g_es[src] + g_ed[dst];
        }
        bool keep = v > 0.0f;
        unsigned mask = __ballot_sync(0xFFFFFFFFu, keep);
        float w = keep ? expf(v - M) : 0.0f;
        sumacc += w;

        while (mask) {
            int l0 = __ffs(mask) - 1; mask &= mask - 1;
            int l1 = -1;
            if (mask) { l1 = __ffs(mask) - 1; mask &= mask - 1; }
            int sl = half ? l1 : l0;
            float ws = __shfl_sync(0xFFFFFFFFu, w,   sl < 0 ? 0 : sl);
            int   ss = __shfl_sync(0xFFFFFFFFu, src, sl < 0 ? 0 : sl);
            int   ds = __shfl_sync(0xFFFFFFFFu, dst, sl < 0 ? 0 : sl);
            if (sl >= 0) {
                float4 vv = *reinterpret_cast<const float4*>(
                    &g_wh[(size_t)ss * OUT_CH + t * 4]);
                float* o = &out[(size_t)ds * OUT_CH + t * 4];
                asm volatile("red.global.add.v4.f32 [%0], {%1, %2, %3, %4};"
                             :: "l"(o), "f"(ws * vv.x), "f"(ws * vv.y),
                                "f"(ws * vv.z), "f"(ws * vv.w)
                             : "memory");
            }
        }
    }

#pragma unroll
    for (int o = 16; o > 0; o >>= 1)
        sumacc += __shfl_xor_sync(0xFFFFFFFFu, sumacc, o);
    if (lane == 0 && sumacc > 0.0f) atomicAdd(&g_sum, sumacc);
}

// ---------------- kernel 3: normalize + ELU in place ----------------
__global__ void elu_kernel(float* __restrict__ out, int total) {
    int i = blockIdx.x * blockDim.x + threadIdx.x;
    if (i >= total / 4) return;
    float S = g_sum;
    float inv = (S > 0.0f) ? (1.0f / S) : 0.0f;
    float4 v = reinterpret_cast<float4*>(out)[i];
    v.x *= inv; v.y *= inv; v.z *= inv; v.w *= inv;
    v.x = (v.x > 0.0f) ? v.x : expm1f(v.x);
    v.y = (v.y > 0.0f) ? v.y : expm1f(v.y);
    v.z = (v.z > 0.0f) ? v.z : expm1f(v.z);
    v.w = (v.w > 0.0f) ? v.w : expm1f(v.w);
    reinterpret_cast<float4*>(out)[i] = v;
}

// ---------------- launch ----------------
extern "C" void kernel_launch(void* const* d_in, const int* in_sizes, int n_in,
                              void* d_out, int out_size) {
    const float* x   = (const float*)d_in[0];
    const void*  ei  = d_in[1];
    const float* W   = (const float*)d_in[2];
    const float* a   = (const float*)d_in[3];
    float*       out = (float*)d_out;

    int n  = in_sizes[0] / IN_CH;   // 50000
    int nE = in_sizes[1] / 2;       // 800000
    int total = n * OUT_CH;

    detect_kernel<<<1, 32>>>((const unsigned int*)ei);
    init_kernel<<<512, 256>>>(out, total);
    wprep_kernel<<<16, 256>>>(W);
    gemm_mma_kernel<<<(n + ROWS_CTA - 1) / ROWS_CTA, 256>>>(x, a, n);
    edge_kernel<<<1184, 256>>>(ei, out, nE);
    elu_kernel<<<(total / 4 + 255) / 256, 256>>>(out, total);
}

// round 15
// speedup vs baseline: 2.8439x; 1.1406x over previous
#include <cuda_runtime.h>
#include <cuda_bf16.h>
#include <math_constants.h>
#include <cstdint>

#define N_NODES_MAX 50000
#define N_EDGES_MAX 800000
#define IN_CH 256
#define OUT_CH 64

// ---------------- scratch (device globals: allocation-free) ----------------
__device__ float g_wh[(size_t)N_NODES_MAX * OUT_CH];   // 12.8 MB
__device__ float g_es[N_NODES_MAX];
__device__ float g_ed[N_NODES_MAX];
__device__ uint4 g_wfb[16][8][32];   // B frags [ks][nb][lane] = {bh0,bh1,bl0,bl1} bf16x2
__device__ float g_maxs;
__device__ float g_maxd;
__device__ float g_sum;
__device__ int   g_is64;

// ---------------- helpers ----------------
__device__ __forceinline__ void atomicMaxF(float* addr, float v) {
    if (v >= 0.0f) atomicMax((int*)addr, __float_as_int(v));
    else           atomicMin((unsigned int*)addr, __float_as_uint(v));
}

__device__ __forceinline__ uint32_t smem_u32(const void* p) {
    uint32_t a;
    asm("{ .reg .u64 t; cvta.to.shared.u64 t, %1; cvt.u32.u64 %0, t; }"
        : "=r"(a) : "l"(p));
    return a;
}

// pack two floats to bf16x2 (f0 -> low half, f1 -> high half)
__device__ __forceinline__ uint32_t bf16x2_pack(float f0, float f1) {
    uint32_t r;
    asm("cvt.rn.bf16x2.f32 %0, %1, %2;" : "=r"(r) : "f"(f1), "f"(f0));
    return r;
}

// hi/lo split of a float pair into bf16x2 regs
__device__ __forceinline__ void bf16_split(float f0, float f1,
                                           uint32_t& h, uint32_t& l) {
    h = bf16x2_pack(f0, f1);
    float g0 = __uint_as_float(h << 16);
    float g1 = __uint_as_float(h & 0xFFFF0000u);
    l = bf16x2_pack(f0 - g0, f1 - g1);
}

// D(16x8) += A(16x16 bf16) * B(16x8 bf16), fp32 accum
__device__ __forceinline__ void mma_bf16(float* c, const uint32_t* a,
                                         uint32_t b0, uint32_t b1) {
    asm volatile(
        "mma.sync.aligned.m16n8k16.row.col.f32.bf16.bf16.f32 "
        "{%0,%1,%2,%3}, {%4,%5,%6,%7}, {%8,%9}, {%0,%1,%2,%3};"
        : "+f"(c[0]), "+f"(c[1]), "+f"(c[2]), "+f"(c[3])
        : "r"(a[0]), "r"(a[1]), "r"(a[2]), "r"(a[3]), "r"(b0), "r"(b1));
}

// ---------------- kernel A: detect edge-index dtype ----------------
__global__ void detect_kernel(const unsigned int* __restrict__ ei_w) {
    if (threadIdx.x == 0) {
        unsigned int any = 0;
        for (int i = 1; i < 256; i += 2) any |= ei_w[i];
        g_is64 = (any == 0) ? 1 : 0;
    }
}

// ---------------- kernel 0: init output + scalars ----------------
__global__ void init_kernel(float* __restrict__ out, int total) {
    int gtid = blockIdx.x * blockDim.x + threadIdx.x;
    if (gtid == 0) {
        g_maxs = -CUDART_INF_F;
        g_maxd = -CUDART_INF_F;
        g_sum = 0.0f;
    }
    float4* o4 = (float4*)out;
    for (int i = gtid; i < total / 4; i += gridDim.x * blockDim.x)
        o4[i] = make_float4(0.f, 0.f, 0.f, 0.f);
}

// ---------------- kernel W: pack W into per-lane bf16 hi/lo B fragments ----
__global__ void wprep_kernel(const float* __restrict__ W) {
    int idx = blockIdx.x * blockDim.x + threadIdx.x;
    if (idx >= 16 * 8 * 32) return;
    int lane = idx & 31, nb = (idx >> 5) & 7, ks = idx >> 8;
    int tig = lane & 3, gid = lane >> 2;
    int nn = nb * 8 + gid;
    int k0 = ks * 16 + 2 * tig;
    float w00 = W[(size_t)k0 * OUT_CH + nn];
    float w01 = W[(size_t)(k0 + 1) * OUT_CH + nn];
    float w10 = W[(size_t)(k0 + 8) * OUT_CH + nn];
    float w11 = W[(size_t)(k0 + 9) * OUT_CH + nn];
    uint4 f;
    bf16_split(w00, w01, f.x, f.z);
    bf16_split(w10, w11, f.y, f.w);
    g_wfb[ks][nb][lane] = f;
}

// ---------------- kernel 1: 3x bf16 mma.sync GEMM, barrier-free mainloop ----
// 8 warps/CTA, 128 rows/CTA, 16 rows/warp; 16 chunks of k=16.
// x staged fp32 via cp.async, 4-stage ring, WARP-PRIVATE rows: each warp
// copies exactly the 16 rows it reads -> no cross-warp smem deps -> no
// __syncthreads in the mainloop. bf16 hi/lo split at consume time from LDS.
#define ROWS_CTA 128
#define RWORDS 20                          // 16 data + 4 pad floats per row
#define STAGEW (ROWS_CTA * RWORDS)         // words per stage (10240 B)
#define NSTAGE 4

__global__ __launch_bounds__(256, 3) void gemm_mma_kernel(
    const float* __restrict__ x, const float* __restrict__ a, int n)
{
    __shared__ __align__(16) float xsm[NSTAGE * STAGEW];   // 40 KB
    __shared__ float as_[2 * OUT_CH];
    const int tid = threadIdx.x, wid = tid >> 5, lane = tid & 31;
    const int gid = lane >> 2, tig = lane & 3;
    if (tid < 128) as_[tid] = a[tid];

    const int row0 = blockIdx.x * ROWS_CTA;
    const uint32_t sb = smem_u32(xsm);

    // warp-private staging: warp wid copies rows [wid*16, wid*16+16).
    // lane covers (row_local, q): i=0 -> rows wid*16 + (lane>>2), i=1 -> +8.
    const int cp_r0 = wid * 16 + (lane >> 2);   // i=0 row
    const int cp_q  = lane & 3;
    const int cg_r0 = row0 + cp_r0;
    const int cg_r1 = cg_r0 + 8;
    const float* src0 = x + (size_t)(cg_r0 < n ? cg_r0 : 0) * IN_CH + cp_q * 4;
    const float* src1 = x + (size_t)(cg_r1 < n ? cg_r1 : 0) * IN_CH + cp_q * 4;
    const uint32_t dst0 = sb + (uint32_t)(cp_r0 * RWORDS + cp_q * 4) * 4u;
    const uint32_t dst1 = dst0 + (uint32_t)(8 * RWORDS) * 4u;
    const int sz0 = (cg_r0 < n) ? 16 : 0;
    const int sz1 = (cg_r1 < n) ? 16 : 0;

    auto prefetch = [&](int c) {
        if (c < 16) {
            uint32_t so = (uint32_t)((c & (NSTAGE - 1)) * STAGEW) * 4u;
            asm volatile("cp.async.cg.shared.global [%0], [%1], 16, %2;"
                         :: "r"(dst0 + so), "l"(src0 + c * 16), "r"(sz0));
            asm volatile("cp.async.cg.shared.global [%0], [%1], 16, %2;"
                         :: "r"(dst1 + so), "l"(src1 + c * 16), "r"(sz1));
        }
        asm volatile("cp.async.commit_group;");
    };

    // consume addresses: rows wid*16+gid (+8), word cols 2tig / 2tig+8
    const uint32_t lds_a = sb + (uint32_t)(((wid * 16 + gid) * RWORDS + 2 * tig) * 4);
    const uint32_t lds_b = lds_a + 8 * RWORDS * 4;   // row +8

    float acc[8][4];
#pragma unroll
    for (int nb = 0; nb < 8; nb++)
#pragma unroll
        for (int j = 0; j < 4; j++) acc[nb][j] = 0.0f;

    prefetch(0); prefetch(1); prefetch(2);

#pragma unroll 4
    for (int c = 0; c < 16; c++) {
        prefetch(c + 3);                       // ring slot (c-1): already consumed
        asm volatile("cp.async.wait_group 3;"); // groups <= c complete
        const uint32_t so = (uint32_t)((c & (NSTAGE - 1)) * STAGEW) * 4u;

        float2 f00, f08, f10, f18;
        asm("ld.shared.v2.f32 {%0,%1}, [%2];" : "=f"(f00.x), "=f"(f00.y) : "r"(lds_a + so));
        asm("ld.shared.v2.f32 {%0,%1}, [%2];" : "=f"(f08.x), "=f"(f08.y) : "r"(lds_b + so));
        asm("ld.shared.v2.f32 {%0,%1}, [%2];" : "=f"(f10.x), "=f"(f10.y) : "r"(lds_a + so + 32));
        asm("ld.shared.v2.f32 {%0,%1}, [%2];" : "=f"(f18.x), "=f"(f18.y) : "r"(lds_b + so + 32));

        uint32_t ah[4], al[4];
        bf16_split(f00.x, f00.y, ah[0], al[0]);
        bf16_split(f08.x, f08.y, ah[1], al[1]);
        bf16_split(f10.x, f10.y, ah[2], al[2]);
        bf16_split(f18.x, f18.y, ah[3], al[3]);

        const uint4* bp = &g_wfb[c][0][lane];
#pragma unroll
        for (int nb = 0; nb < 8; nb++) {
            uint4 b = __ldg(bp + nb * 32);
            mma_bf16(acc[nb], ah, b.x, b.y);   // hi*hi
            mma_bf16(acc[nb], ah, b.z, b.w);   // hi*lo
            mma_bf16(acc[nb], al, b.x, b.y);   // lo*hi
        }
    }

    __syncthreads();   // as_ visibility for warps 4-7 (written by tid<128)

    // ---- epilogue: wh stores + es/ed dots + maxes ----
    const int r0 = row0 + wid * 16 + gid;
    const int r8 = r0 + 8;
    const bool v0 = r0 < n, v8 = r8 < n;
    float es0 = 0.f, ed0 = 0.f, es8 = 0.f, ed8 = 0.f;
#pragma unroll
    for (int nb = 0; nb < 8; nb++) {
        int c0 = nb * 8 + 2 * tig;
        es0 += acc[nb][0] * as_[c0] + acc[nb][1] * as_[c0 + 1];
        ed0 += acc[nb][0] * as_[OUT_CH + c0] + acc[nb][1] * as_[OUT_CH + c0 + 1];
        es8 += acc[nb][2] * as_[c0] + acc[nb][3] * as_[c0 + 1];
        ed8 += acc[nb][2] * as_[OUT_CH + c0] + acc[nb][3] * as_[OUT_CH + c0 + 1];
        if (v0) *(float2*)&g_wh[(size_t)r0 * OUT_CH + c0] =
            make_float2(acc[nb][0], acc[nb][1]);
        if (v8) *(float2*)&g_wh[(size_t)r8 * OUT_CH + c0] =
            make_float2(acc[nb][2], acc[nb][3]);
    }
#pragma unroll
    for (int o = 1; o <= 2; o <<= 1) {
        es0 += __shfl_xor_sync(0xFFFFFFFFu, es0, o);
        ed0 += __shfl_xor_sync(0xFFFFFFFFu, ed0, o);
        es8 += __shfl_xor_sync(0xFFFFFFFFu, es8, o);
        ed8 += __shfl_xor_sync(0xFFFFFFFFu, ed8, o);
    }
    if (tig == 0 && v0) { g_es[r0] = es0; g_ed[r0] = ed0; }
    if (tig == 0 && v8) { g_es[r8] = es8; g_ed[r8] = ed8; }

    float ms = fmaxf(v0 ? es0 : -CUDART_INF_F, v8 ? es8 : -CUDART_INF_F);
    float md = fmaxf(v0 ? ed0 : -CUDART_INF_F, v8 ? ed8 : -CUDART_INF_F);
#pragma unroll
    for (int o = 16; o > 0; o >>= 1) {
        ms = fmaxf(ms, __shfl_xor_sync(0xFFFFFFFFu, ms, o));
        md = fmaxf(md, __shfl_xor_sync(0xFFFFFFFFu, md, o));
    }
    if (lane == 0) {
        atomicMaxF(&g_maxs, ms);
        atomicMaxF(&g_maxd, md);
    }
}

// ---------------- kernel 2: FUSED edge pass (unchanged) ----------------
// Masked edges have weight exp(NEG_BIG-M) == +0.0 exactly, so skipping them
// is bit-identical. M = max(es)+max(ed) >= true max: valid softmax shift.
__global__ void edge_kernel(const void* __restrict__ ei_raw,
                            float* __restrict__ out, int nE) {
    const int lane   = threadIdx.x & 31;
    const int warpId = (blockIdx.x * blockDim.x + threadIdx.x) >> 5;
    const int nWarps = (gridDim.x * blockDim.x) >> 5;
    const int is64   = g_is64;
    const float M    = g_maxs + g_maxd;
    const int half   = lane >> 4;
    const int t      = lane & 15;

    float sumacc = 0.0f;

    for (int base = warpId * 32; base < nE; base += nWarps * 32) {
        int e = base + lane;
        int src = 0, dst = 0;
        float v = -1.0f;
        if (e < nE) {
            if (is64) {
                src = (int)((const long long*)ei_raw)[e];
                dst = (int)((const long long*)ei_raw)[nE + e];
            } else {
                src = ((const int*)ei_raw)[e];
                dst = ((const int*)ei_raw)[nE + e];
            }
            v = g_es[src] + g_ed[dst];
        }
        bool keep = v > 0.0f;
        unsigned mask = __ballot_sync(0xFFFFFFFFu, keep);
        float w = keep ? expf(v - M) : 0.0f;
        sumacc += w;

        while (mask) {
            int l0 = __ffs(mask) - 1; mask &= mask - 1;
            int l1 = -1;
            if (mask) { l1 = __ffs(mask) - 1; mask &= mask - 1; }
            int sl = half ? l1 : l0;
            float ws = __shfl_sync(0xFFFFFFFFu, w,   sl < 0 ? 0 : sl);
            int   ss = __shfl_sync(0xFFFFFFFFu, src, sl < 0 ? 0 : sl);
            int   ds = __shfl_sync(0xFFFFFFFFu, dst, sl < 0 ? 0 : sl);
            if (sl >= 0) {
                float4 vv = *reinterpret_cast<const float4*>(
                    &g_wh[(size_t)ss * OUT_CH + t * 4]);
                float* o = &out[(size_t)ds * OUT_CH + t * 4];
                asm volatile("red.global.add.v4.f32 [%0], {%1, %2, %3, %4};"
                             :: "l"(o), "f"(ws * vv.x), "f"(ws * vv.y),
                                "f"(ws * vv.z), "f"(ws * vv.w)
                             : "memory");
            }
        }
    }

#pragma unroll
    for (int o = 16; o > 0; o >>= 1)
        sumacc += __shfl_xor_sync(0xFFFFFFFFu, sumacc, o);
    if (lane == 0 && sumacc > 0.0f) atomicAdd(&g_sum, sumacc);
}

// ---------------- kernel 3: normalize + ELU in place ----------------
__global__ void elu_kernel(float* __restrict__ out, int total) {
    int i = blockIdx.x * blockDim.x + threadIdx.x;
    if (i >= total / 4) return;
    float S = g_sum;
    float inv = (S > 0.0f) ? (1.0f / S) : 0.0f;
    float4 v = reinterpret_cast<float4*>(out)[i];
    v.x *= inv; v.y *= inv; v.z *= inv; v.w *= inv;
    v.x = (v.x > 0.0f) ? v.x : expm1f(v.x);
    v.y = (v.y > 0.0f) ? v.y : expm1f(v.y);
    v.z = (v.z > 0.0f) ? v.z : expm1f(v.z);
    v.w = (v.w > 0.0f) ? v.w : expm1f(v.w);
    reinterpret_cast<float4*>(out)[i] = v;
}

// ---------------- launch ----------------
extern "C" void kernel_launch(void* const* d_in, const int* in_sizes, int n_in,
                              void* d_out, int out_size) {
    const float* x   = (const float*)d_in[0];
    const void*  ei  = d_in[1];
    const float* W   = (const float*)d_in[2];
    const float* a   = (const float*)d_in[3];
    float*       out = (float*)d_out;

    int n  = in_sizes[0] / IN_CH;   // 50000
    int nE = in_sizes[1] / 2;       // 800000
    int total = n * OUT_CH;

    detect_kernel<<<1, 32>>>((const unsigned int*)ei);
    init_kernel<<<512, 256>>>(out, total);
    wprep_kernel<<<16, 256>>>(W);
    gemm_mma_kernel<<<(n + ROWS_CTA - 1) / ROWS_CTA, 256>>>(x, a, n);
    edge_kernel<<<1184, 256>>>(ei, out, nE);
    elu_kernel<<<(total / 4 + 255) / 256, 256>>>(out, total);
}

// round 17
// speedup vs baseline: 2.9295x; 1.0301x over previous
#include <cuda_runtime.h>
#include <cuda_bf16.h>
#include <math_constants.h>
#include <cstdint>

#define N_NODES_MAX 50000
#define N_EDGES_MAX 800000
#define IN_CH 256
#define OUT_CH 64

// ---------------- scratch (device globals: allocation-free) ----------------
__device__ float g_wh[(size_t)N_NODES_MAX * OUT_CH];   // 12.8 MB
__device__ float g_es[N_NODES_MAX];
__device__ float g_ed[N_NODES_MAX];
__device__ uint4 g_wfb[16][8][32];   // B frags [ks][nb][lane] = {bh0,bh1,bl0,bl1} bf16x2
__device__ float g_maxs;
__device__ float g_maxd;
__device__ float g_sum;
__device__ int   g_is64;

// ---------------- helpers ----------------
__device__ __forceinline__ void atomicMaxF(float* addr, float v) {
    if (v >= 0.0f) atomicMax((int*)addr, __float_as_int(v));
    else           atomicMin((unsigned int*)addr, __float_as_uint(v));
}

__device__ __forceinline__ uint32_t smem_u32(const void* p) {
    uint32_t a;
    asm("{ .reg .u64 t; cvta.to.shared.u64 t, %1; cvt.u32.u64 %0, t; }"
        : "=r"(a) : "l"(p));
    return a;
}

// pack two floats to bf16x2 (f0 -> low half, f1 -> high half)
__device__ __forceinline__ uint32_t bf16x2_pack(float f0, float f1) {
    uint32_t r;
    asm("cvt.rn.bf16x2.f32 %0, %1, %2;" : "=r"(r) : "f"(f1), "f"(f0));
    return r;
}

// hi/lo split of a float pair into bf16x2 regs
__device__ __forceinline__ void bf16_split(float f0, float f1,
                                           uint32_t& h, uint32_t& l) {
    h = bf16x2_pack(f0, f1);
    float g0 = __uint_as_float(h << 16);
    float g1 = __uint_as_float(h & 0xFFFF0000u);
    l = bf16x2_pack(f0 - g0, f1 - g1);
}

// D(16x8) += A(16x16 bf16) * B(16x8 bf16), fp32 accum
__device__ __forceinline__ void mma_bf16(float* c, const uint32_t* a,
                                         uint32_t b0, uint32_t b1) {
    asm volatile(
        "mma.sync.aligned.m16n8k16.row.col.f32.bf16.bf16.f32 "
        "{%0,%1,%2,%3}, {%4,%5,%6,%7}, {%8,%9}, {%0,%1,%2,%3};"
        : "+f"(c[0]), "+f"(c[1]), "+f"(c[2]), "+f"(c[3])
        : "r"(a[0]), "r"(a[1]), "r"(a[2]), "r"(a[3]), "r"(b0), "r"(b1));
}

// ---------------- kernel 0: setup (init + detect + wprep fused) ----------
// gtid 0: scalars + edge-dtype detect (int64 indices < 2^31 have all-zero
// high words; genuine int32 data has random values at odd positions).
// gtid < 4096: W fragment prep. All: zero the output.
__global__ void setup_kernel(float* __restrict__ out, int total,
                             const float* __restrict__ W,
                             const unsigned int* __restrict__ ei_w) {
    int gtid = blockIdx.x * blockDim.x + threadIdx.x;
    if (gtid == 0) {
        g_maxs = -CUDART_INF_F;
        g_maxd = -CUDART_INF_F;
        g_sum = 0.0f;
        unsigned int any = 0;
        for (int i = 1; i < 256; i += 2) any |= ei_w[i];
        g_is64 = (any == 0) ? 1 : 0;
    }
    if (gtid < 16 * 8 * 32) {
        int lane = gtid & 31, nb = (gtid >> 5) & 7, ks = gtid >> 8;
        int tig = lane & 3, gid = lane >> 2;
        int nn = nb * 8 + gid;
        int k0 = ks * 16 + 2 * tig;
        float w00 = W[(size_t)k0 * OUT_CH + nn];
        float w01 = W[(size_t)(k0 + 1) * OUT_CH + nn];
        float w10 = W[(size_t)(k0 + 8) * OUT_CH + nn];
        float w11 = W[(size_t)(k0 + 9) * OUT_CH + nn];
        uint4 f;
        bf16_split(w00, w01, f.x, f.z);
        bf16_split(w10, w11, f.y, f.w);
        g_wfb[ks][nb][lane] = f;
    }
    float4* o4 = (float4*)out;
    for (int i = gtid; i < total / 4; i += gridDim.x * blockDim.x)
        o4[i] = make_float4(0.f, 0.f, 0.f, 0.f);
}

// ---------------- kernel 1: 3x bf16 mma.sync GEMM, barrier-free mainloop ----
// 8 warps/CTA, 128 rows/CTA, 16 rows/warp; 16 chunks of k=16.
// x staged fp32 via cp.async, 4-stage ring, WARP-PRIVATE rows (no mainloop
// __syncthreads). MMAs issued PASS-MAJOR in groups of 4 accumulators:
// RAW chain distance 4 instead of 1 -> HMMA latency covered.
#define ROWS_CTA 128
#define RWORDS 20                          // 16 data + 4 pad floats per row
#define STAGEW (ROWS_CTA * RWORDS)         // words per stage (10240 B)
#define NSTAGE 4

__global__ __launch_bounds__(256, 3) void gemm_mma_kernel(
    const float* __restrict__ x, const float* __restrict__ a, int n)
{
    __shared__ __align__(16) float xsm[NSTAGE * STAGEW];   // 40 KB
    __shared__ float as_[2 * OUT_CH];
    const int tid = threadIdx.x, wid = tid >> 5, lane = tid & 31;
    const int gid = lane >> 2, tig = lane & 3;
    if (tid < 128) as_[tid] = a[tid];

    const int row0 = blockIdx.x * ROWS_CTA;
    const uint32_t sb = smem_u32(xsm);

    // warp-private staging: warp wid copies rows [wid*16, wid*16+16).
    const int cp_r0 = wid * 16 + (lane >> 2);
    const int cp_q  = lane & 3;
    const int cg_r0 = row0 + cp_r0;
    const int cg_r1 = cg_r0 + 8;
    const float* src0 = x + (size_t)(cg_r0 < n ? cg_r0 : 0) * IN_CH + cp_q * 4;
    const float* src1 = x + (size_t)(cg_r1 < n ? cg_r1 : 0) * IN_CH + cp_q * 4;
    const uint32_t dst0 = sb + (uint32_t)(cp_r0 * RWORDS + cp_q * 4) * 4u;
    const uint32_t dst1 = dst0 + (uint32_t)(8 * RWORDS) * 4u;
    const int sz0 = (cg_r0 < n) ? 16 : 0;
    const int sz1 = (cg_r1 < n) ? 16 : 0;

    auto prefetch = [&](int c) {
        if (c < 16) {
            uint32_t so = (uint32_t)((c & (NSTAGE - 1)) * STAGEW) * 4u;
            asm volatile("cp.async.cg.shared.global [%0], [%1], 16, %2;"
                         :: "r"(dst0 + so), "l"(src0 + c * 16), "r"(sz0));
            asm volatile("cp.async.cg.shared.global [%0], [%1], 16, %2;"
                         :: "r"(dst1 + so), "l"(src1 + c * 16), "r"(sz1));
        }
        asm volatile("cp.async.commit_group;");
    };

    // consume addresses: rows wid*16+gid (+8), word cols 2tig / 2tig+8
    const uint32_t lds_a = sb + (uint32_t)(((wid * 16 + gid) * RWORDS + 2 * tig) * 4);
    const uint32_t lds_b = lds_a + 8 * RWORDS * 4;

    float acc[8][4];
#pragma unroll
    for (int nb = 0; nb < 8; nb++)
#pragma unroll
        for (int j = 0; j < 4; j++) acc[nb][j] = 0.0f;

    prefetch(0); prefetch(1); prefetch(2);

#pragma unroll 4
    for (int c = 0; c < 16; c++) {
        prefetch(c + 3);
        asm volatile("cp.async.wait_group 3;");
        const uint32_t so = (uint32_t)((c & (NSTAGE - 1)) * STAGEW) * 4u;

        float2 f00, f08, f10, f18;
        asm("ld.shared.v2.f32 {%0,%1}, [%2];" : "=f"(f00.x), "=f"(f00.y) : "r"(lds_a + so));
        asm("ld.shared.v2.f32 {%0,%1}, [%2];" : "=f"(f08.x), "=f"(f08.y) : "r"(lds_b + so));
        asm("ld.shared.v2.f32 {%0,%1}, [%2];" : "=f"(f10.x), "=f"(f10.y) : "r"(lds_a + so + 32));
        asm("ld.shared.v2.f32 {%0,%1}, [%2];" : "=f"(f18.x), "=f"(f18.y) : "r"(lds_b + so + 32));

        uint32_t ah[4], al[4];
        bf16_split(f00.x, f00.y, ah[0], al[0]);
        bf16_split(f08.x, f08.y, ah[1], al[1]);
        bf16_split(f10.x, f10.y, ah[2], al[2]);
        bf16_split(f18.x, f18.y, ah[3], al[3]);

        const uint4* bp = &g_wfb[c][0][lane];
#pragma unroll
        for (int g = 0; g < 2; g++) {
            uint4 b0 = __ldg(bp + (4 * g + 0) * 32);
            uint4 b1 = __ldg(bp + (4 * g + 1) * 32);
            uint4 b2 = __ldg(bp + (4 * g + 2) * 32);
            uint4 b3 = __ldg(bp + (4 * g + 3) * 32);
            float* A0 = acc[4 * g + 0];
            float* A1 = acc[4 * g + 1];
            float* A2 = acc[4 * g + 2];
            float* A3 = acc[4 * g + 3];
            // pass hi*hi (4 independent chains)
            mma_bf16(A0, ah, b0.x, b0.y);
            mma_bf16(A1, ah, b1.x, b1.y);
            mma_bf16(A2, ah, b2.x, b2.y);
            mma_bf16(A3, ah, b3.x, b3.y);
            // pass hi*lo
            mma_bf16(A0, ah, b0.z, b0.w);
            mma_bf16(A1, ah, b1.z, b1.w);
            mma_bf16(A2, ah, b2.z, b2.w);
            mma_bf16(A3, ah, b3.z, b3.w);
            // pass lo*hi
            mma_bf16(A0, al, b0.x, b0.y);
            mma_bf16(A1, al, b1.x, b1.y);
            mma_bf16(A2, al, b2.x, b2.y);
            mma_bf16(A3, al, b3.x, b3.y);
        }
    }

    __syncthreads();   // as_ visibility for warps 4-7

    // ---- epilogue: wh stores + es/ed dots + maxes ----
    const int r0 = row0 + wid * 16 + gid;
    const int r8 = r0 + 8;
    const bool v0 = r0 < n, v8 = r8 < n;
    float es0 = 0.f, ed0 = 0.f, es8 = 0.f, ed8 = 0.f;
#pragma unroll
    for (int nb = 0; nb < 8; nb++) {
        int c0 = nb * 8 + 2 * tig;
        es0 += acc[nb][0] * as_[c0] + acc[nb][1] * as_[c0 + 1];
        ed0 += acc[nb][0] * as_[OUT_CH + c0] + acc[nb][1] * as_[OUT_CH + c0 + 1];
        es8 += acc[nb][2] * as_[c0] + acc[nb][3] * as_[c0 + 1];
        ed8 += acc[nb][2] * as_[OUT_CH + c0] + acc[nb][3] * as_[OUT_CH + c0 + 1];
        if (v0) *(float2*)&g_wh[(size_t)r0 * OUT_CH + c0] =
            make_float2(acc[nb][0], acc[nb][1]);
        if (v8) *(float2*)&g_wh[(size_t)r8 * OUT_CH + c0] =
            make_float2(acc[nb][2], acc[nb][3]);
    }
#pragma unroll
    for (int o = 1; o <= 2; o <<= 1) {
        es0 += __shfl_xor_sync(0xFFFFFFFFu, es0, o);
        ed0 += __shfl_xor_sync(0xFFFFFFFFu, ed0, o);
        es8 += __shfl_xor_sync(0xFFFFFFFFu, es8, o);
        ed8 += __shfl_xor_sync(0xFFFFFFFFu, ed8, o);
    }
    if (tig == 0 && v0) { g_es[r0] = es0; g_ed[r0] = ed0; }
    if (tig == 0 && v8) { g_es[r8] = es8; g_ed[r8] = ed8; }

    float ms = fmaxf(v0 ? es0 : -CUDART_INF_F, v8 ? es8 : -CUDART_INF_F);
    float md = fmaxf(v0 ? ed0 : -CUDART_INF_F, v8 ? ed8 : -CUDART_INF_F);
#pragma unroll
    for (int o = 16; o > 0; o >>= 1) {
        ms = fmaxf(ms, __shfl_xor_sync(0xFFFFFFFFu, ms, o));
        md = fmaxf(md, __shfl_xor_sync(0xFFFFFFFFu, md, o));
    }
    if (lane == 0) {
        atomicMaxF(&g_maxs, ms);
        atomicMaxF(&g_maxd, md);
    }
}

// ---------------- kernel 2: FUSED edge pass (unchanged) ----------------
// Masked edges have weight exp(NEG_BIG-M) == +0.0 exactly, so skipping them
// is bit-identical. M = max(es)+max(ed) >= true max: valid softmax shift.
__global__ void edge_kernel(const void* __restrict__ ei_raw,
                            float* __restrict__ out, int nE) {
    const int lane   = threadIdx.x & 31;
    const int warpId = (blockIdx.x * blockDim.x + threadIdx.x) >> 5;
    const int nWarps = (gridDim.x * blockDim.x) >> 5;
    const int is64   = g_is64;
    const float M    = g_maxs + g_maxd;
    const int half   = lane >> 4;
    const int t      = lane & 15;

    float sumacc = 0.0f;

    for (int base = warpId * 32; base < nE; base += nWarps * 32) {
        int e = base + lane;
        int src = 0, dst = 0;
        float v = -1.0f;
        if (e < nE) {
            if (is64) {
                src = (int)((const long long*)ei_raw)[e];
                dst = (int)((const long long*)ei_raw)[nE + e];
            } else {
                src = ((const int*)ei_raw)[e];
                dst = ((const int*)ei_raw)[nE + e];
            }
            v = g_es[src] + g_ed[dst];
        }
        bool keep = v > 0.0f;
        unsigned mask = __ballot_sync(0xFFFFFFFFu, keep);
        float w = keep ? expf(v - M) : 0.0f;
        sumacc += w;

        while (mask) {
            int l0 = __ffs(mask) - 1; mask &= mask - 1;
            int l1 = -1;
            if (mask) { l1 = __ffs(mask) - 1; mask &= mask - 1; }
            int sl = half ? l1 : l0;
            float ws = __shfl_sync(0xFFFFFFFFu, w,   sl < 0 ? 0 : sl);
            int   ss = __shfl_sync(0xFFFFFFFFu, src, sl < 0 ? 0 : sl);
            int   ds = __shfl_sync(0xFFFFFFFFu, dst, sl < 0 ? 0 : sl);
            if (sl >= 0) {
                float4 vv = *reinterpret_cast<const float4*>(
                    &g_wh[(size_t)ss * OUT_CH + t * 4]);
                float* o = &out[(size_t)ds * OUT_CH + t * 4];
                asm volatile("red.global.add.v4.f32 [%0], {%1, %2, %3, %4};"
                             :: "l"(o), "f"(ws * vv.x), "f"(ws * vv.y),
                                "f"(ws * vv.z), "f"(ws * vv.w)
                             : "memory");
            }
        }
    }

#pragma unroll
    for (int o = 16; o > 0; o >>= 1)
        sumacc += __shfl_xor_sync(0xFFFFFFFFu, sumacc, o);
    if (lane == 0 && sumacc > 0.0f) atomicAdd(&g_sum, sumacc);
}

// ---------------- kernel 3: normalize + ELU in place ----------------
__global__ void elu_kernel(float* __restrict__ out, int total) {
    int i = blockIdx.x * blockDim.x + threadIdx.x;
    if (i >= total / 4) return;
    float S = g_sum;
    float inv = (S > 0.0f) ? (1.0f / S) : 0.0f;
    float4 v = reinterpret_cast<float4*>(out)[i];
    v.x *= inv; v.y *= inv; v.z *= inv; v.w *= inv;
    v.x = (v.x > 0.0f) ? v.x : expm1f(v.x);
    v.y = (v.y > 0.0f) ? v.y : expm1f(v.y);
    v.z = (v.z > 0.0f) ? v.z : expm1f(v.z);
    v.w = (v.w > 0.0f) ? v.w : expm1f(v.w);
    reinterpret_cast<float4*>(out)[i] = v;
}

// ---------------- launch ----------------
extern "C" void kernel_launch(void* const* d_in, const int* in_sizes, int n_in,
                              void* d_out, int out_size) {
    const float* x   = (const float*)d_in[0];
    const void*  ei  = d_in[1];
    const float* W   = (const float*)d_in[2];
    const float* a   = (const float*)d_in[3];
    float*       out = (float*)d_out;

    int n  = in_sizes[0] / IN_CH;   // 50000
    int nE = in_sizes[1] / 2;       // 800000
    int total = n * OUT_CH;

    setup_kernel<<<512, 256>>>(out, total, W, (const unsigned int*)ei);
    gemm_mma_kernel<<<(n + ROWS_CTA - 1) / ROWS_CTA, 256>>>(x, a, n);
    edge_kernel<<<1184, 256>>>(ei, out, nE);
    elu_kernel<<<(total / 4 + 255) / 256, 256>>>(out, total);
}